// round 2
// baseline (speedup 1.0000x reference)
#include <cuda_runtime.h>
#include <math.h>

#define BS    32
#define SEQ   2048
#define ENC   512
#define HEADS 8
#define IH    1024
#define DECIN 1024   // DEC + ENC

// ---------------- scratch (static device globals; no allocation) ----------------
__device__ float g_qv[BS][IH];          // dec@Wq + bq + bv
__device__ float g_beta[BS][HEADS];
__device__ float g_kap[BS][HEADS];
__device__ int   g_lo[BS];
__device__ int   g_hi[BS];
__device__ float g_pf[BS][4][SEQ][HEADS];   // partial h@Wf per j-tile
__device__ float g_ctx[BS][HEADS * ENC];    // context before Wfc

__device__ __forceinline__ float softplusf(float x) {
    // matches jax.nn.softplus = max(x,0) + log1p(exp(-|x|))
    return fmaxf(x, 0.f) + log1pf(expf(-fabsf(x)));
}

// ---------------- K0: heads projections (beta, kappa), active window ----------------
__global__ void k0_heads(const float* __restrict__ dec, const float* __restrict__ kappa_in,
                         const float* __restrict__ Wb, const float* __restrict__ bb,
                         const float* __restrict__ Wk, const float* __restrict__ bk,
                         float* __restrict__ out_kappa) {
    int b = blockIdx.x;
    __shared__ float sdec[DECIN];
    for (int i = threadIdx.x; i < DECIN; i += blockDim.x)
        sdec[i] = dec[b * DECIN + i];
    __syncthreads();
    __shared__ float sbeta[HEADS], skap[HEADS];
    int t = threadIdx.x;
    if (t < 16) {
        int h = t & 7;
        const float* W = (t < 8) ? Wb : Wk;
        float acc = 0.f;
        for (int k = 0; k < DECIN; k++) acc += sdec[k] * W[k * HEADS + h];
        if (t < 8) {
            float bv = softplusf(acc + bb[h]);
            sbeta[h] = bv;
            g_beta[b][h] = bv;
        } else {
            float kv = kappa_in[b * HEADS + h] + softplusf(acc + bk[h]);
            skap[h] = kv;
            g_kap[b][h] = kv;
            out_kappa[b * HEADS + h] = kv;
        }
    }
    __syncthreads();
    if (t == 0) {
        float lof = 1e30f, hif = -1e30f;
        for (int h = 0; h < HEADS; h++) {
            float R = sqrtf(110.f / sbeta[h]);   // outside: beta*d^2 > 110 -> expf == 0 exactly
            lof = fminf(lof, skap[h] - R);
            hif = fmaxf(hif, skap[h] + R);
        }
        int lo, hi;
        if (hif < 0.f || lof > (float)(SEQ - 1)) { lo = 0; hi = -1; }
        else {
            lo = (int)floorf(lof); if (lo < 0) lo = 0;
            hi = (int)ceilf(hif);  if (hi > SEQ - 1) hi = SEQ - 1;
        }
        g_lo[b] = lo; g_hi[b] = hi;
    }
}

// ---------------- K1: qv = dec@Wq + bq + bv ----------------
// grid (16 j-tiles of 64, 8 batch-groups of 4), block 256 = (c:64, ks:4)
__global__ void k1_query(const float* __restrict__ dec, const float* __restrict__ Wq,
                         const float* __restrict__ bq, const float* __restrict__ bv) {
    int jt = blockIdx.x, bg = blockIdx.y;
    int c  = threadIdx.x & 63;
    int ks = threadIdx.x >> 6;
    int j  = jt * 64 + c;
    __shared__ float sdec[4][DECIN];
    for (int i = threadIdx.x; i < 4 * DECIN; i += 256) {
        int bb = i >> 10, k = i & (DECIN - 1);
        sdec[bb][k] = dec[(bg * 4 + bb) * DECIN + k];
    }
    __syncthreads();
    float a0 = 0.f, a1 = 0.f, a2 = 0.f, a3 = 0.f;
    int k0 = ks * 256;
    #pragma unroll 4
    for (int k = k0; k < k0 + 256; k++) {
        float w = Wq[k * IH + j];
        a0 += sdec[0][k] * w; a1 += sdec[1][k] * w;
        a2 += sdec[2][k] * w; a3 += sdec[3][k] * w;
    }
    __shared__ float pacc[4][4][64];
    pacc[ks][0][c] = a0; pacc[ks][1][c] = a1;
    pacc[ks][2][c] = a2; pacc[ks][3][c] = a3;
    __syncthreads();
    if (ks == 0) {
        float add = bq[j] + bv[j];
        #pragma unroll
        for (int bb = 0; bb < 4; bb++) {
            float s = pacc[0][bb][c] + pacc[1][bb][c] + pacc[2][bb][c] + pacc[3][bb][c];
            g_qv[bg * 4 + bb][j] = s + add;
        }
    }
}

// ---------------- K2a: value slice GEMM + tanh + partial @Wf ----------------
// grid (64 row-chunks of 32, 4 j-tiles of 256, 32 batches), block 256 = (tx:32, ty:8)
// thread tile: 4 rows x 8 cols
#define KK 16
__global__ void __launch_bounds__(256) k2a_value(const float* __restrict__ enc,
                                                 const float* __restrict__ Wv,
                                                 const float* __restrict__ Wf) {
    int chunk = blockIdx.x;
    int jt    = blockIdx.y;
    int b     = blockIdx.z;
    int lo = g_lo[b], hi = g_hi[b];
    int s0 = lo + chunk * 32;
    if (s0 > hi) return;
    int nrows = hi - s0 + 1; if (nrows > 32) nrows = 32;
    int W = hi - lo + 1;
    int jbase = jt * 256;
    int tx = threadIdx.x & 31;
    int ty = threadIdx.x >> 5;

    __shared__ float sWv[KK][256];
    __shared__ float sEnc[KK][36];   // stride 36: 16B aligned rows, low write conflicts

    float acc[4][8];
    #pragma unroll
    for (int r = 0; r < 4; r++)
        #pragma unroll
        for (int c = 0; c < 8; c++) acc[r][c] = 0.f;

    const float* encb = enc + (size_t)b * SEQ * ENC;

    for (int kk = 0; kk < ENC; kk += KK) {
        for (int idx = threadIdx.x; idx < KK * 256; idx += 256) {
            int k = idx >> 8, jj = idx & 255;
            sWv[k][jj] = Wv[(kk + k) * IH + jbase + jj];
        }
        for (int idx = threadIdx.x; idx < KK * 32; idx += 256) {
            int r = idx >> 4, k = idx & 15;
            sEnc[k][r] = (r < nrows) ? encb[(size_t)(s0 + r) * ENC + kk + k] : 0.f;
        }
        __syncthreads();
        #pragma unroll
        for (int k = 0; k < KK; k++) {
            float4 e  = *(const float4*)&sEnc[k][ty * 4];
            float4 w0 = *(const float4*)&sWv[k][tx * 8];
            float4 w1 = *(const float4*)&sWv[k][tx * 8 + 4];
            float ev[4] = {e.x, e.y, e.z, e.w};
            float wv[8] = {w0.x, w0.y, w0.z, w0.w, w1.x, w1.y, w1.z, w1.w};
            #pragma unroll
            for (int r = 0; r < 4; r++)
                #pragma unroll
                for (int c = 0; c < 8; c++)
                    acc[r][c] += ev[r] * wv[c];
        }
        __syncthreads();
    }

    // epilogue: h = tanh(qv + value); pf[r][h] += h * Wf[j][h]
    float pf[4][8];
    #pragma unroll
    for (int r = 0; r < 4; r++)
        #pragma unroll
        for (int h = 0; h < 8; h++) pf[r][h] = 0.f;

    #pragma unroll
    for (int cc = 0; cc < 8; cc++) {
        int j = jbase + tx * 8 + cc;
        float q = g_qv[b][j];
        float4 wa = *(const float4*)&Wf[j * 8];
        float4 wb = *(const float4*)&Wf[j * 8 + 4];
        float wf[8] = {wa.x, wa.y, wa.z, wa.w, wb.x, wb.y, wb.z, wb.w};
        #pragma unroll
        for (int r = 0; r < 4; r++) {
            float hv = tanhf(q + acc[r][cc]);
            #pragma unroll
            for (int h = 0; h < 8; h++) pf[r][h] += hv * wf[h];
        }
    }

    // deterministic warp butterfly reduction over tx (j within tile)
    #pragma unroll
    for (int r = 0; r < 4; r++)
        #pragma unroll
        for (int h = 0; h < 8; h++)
            #pragma unroll
            for (int off = 16; off >= 1; off >>= 1)
                pf[r][h] += __shfl_xor_sync(0xffffffffu, pf[r][h], off);

    if (tx == 0) {
        #pragma unroll
        for (int r = 0; r < 4; r++) {
            int lrow = ty * 4 + r;
            if (lrow < nrows) {
                int srel = chunk * 32 + lrow;
                if (srel < W) {
                    #pragma unroll
                    for (int h = 0; h < 8; h++)
                        g_pf[b][jt][srel][h] = pf[r][h];
                }
            }
        }
    }
}

// ---------------- K2b: combine partials -> alpha -> score ----------------
__global__ void k2b_score(const float* __restrict__ bf, const float* __restrict__ mask,
                          float* __restrict__ out_score) {
    int b = blockIdx.x;
    int lo = g_lo[b], hi = g_hi[b];
    int W = hi - lo + 1;
    for (int idx = threadIdx.x; idx < W * HEADS; idx += blockDim.x) {
        int srel = idx >> 3, h = idx & 7;
        int s = lo + srel;
        float f = g_pf[b][0][srel][h] + g_pf[b][1][srel][h] +
                  g_pf[b][2][srel][h] + g_pf[b][3][srel][h] + bf[h];
        float alpha = softplusf(f) * mask[b * SEQ + s];
        float d = g_kap[b][h] - (float)s;
        out_score[((size_t)b * SEQ + s) * HEADS + h] = alpha * expf(-g_beta[b][h] * d * d);
    }
}

// ---------------- K3: context_raw[b,h,e] = sum_s score*enc ----------------
__global__ void k3_ctx(const float* __restrict__ enc, const float* __restrict__ score) {
    int b = blockIdx.x;
    int lo = g_lo[b], hi = g_hi[b];
    for (int idx = threadIdx.x; idx < HEADS * ENC; idx += blockDim.x) {
        int h = idx >> 9, e = idx & 511;
        float acc = 0.f;
        for (int s = lo; s <= hi; s++)
            acc += score[((size_t)b * SEQ + s) * HEADS + h] *
                   enc[((size_t)b * SEQ + s) * ENC + e];
        g_ctx[b][idx] = acc;
    }
}

// ---------------- K4: context = context_raw @ Wfc + bfc ----------------
// grid (8 e-tiles of 64, 8 batch-groups of 4), block 256 = (c:64, bl:4)
__global__ void k4_final(const float* __restrict__ Wfc, const float* __restrict__ bfc,
                         float* __restrict__ out_ctx) {
    int eb = blockIdx.x, bg = blockIdx.y;
    int c  = threadIdx.x & 63;
    int bl = threadIdx.x >> 6;
    int e  = eb * 64 + c;
    int b  = bg * 4 + bl;
    const float* ctx = g_ctx[b];
    float a0 = 0.f, a1 = 0.f, a2 = 0.f, a3 = 0.f;
    for (int j = 0; j < HEADS * ENC; j += 4) {
        a0 += ctx[j + 0] * Wfc[(j + 0) * ENC + e];
        a1 += ctx[j + 1] * Wfc[(j + 1) * ENC + e];
        a2 += ctx[j + 2] * Wfc[(j + 2) * ENC + e];
        a3 += ctx[j + 3] * Wfc[(j + 3) * ENC + e];
    }
    out_ctx[b * ENC + e] = (a0 + a1) + (a2 + a3) + bfc[e];
}

// ---------------- launch ----------------
extern "C" void kernel_launch(void* const* d_in, const int* in_sizes, int n_in,
                              void* d_out, int out_size) {
    const float* enc   = (const float*)d_in[0];
    const float* dec   = (const float*)d_in[1];
    const float* kappa = (const float*)d_in[2];
    const float* mask  = (const float*)d_in[3];
    const float* Wv    = (const float*)d_in[4];
    const float* bv    = (const float*)d_in[5];
    const float* Wq    = (const float*)d_in[6];
    const float* bq    = (const float*)d_in[7];
    const float* Wf    = (const float*)d_in[8];
    const float* bf    = (const float*)d_in[9];
    const float* Wb    = (const float*)d_in[10];
    const float* bb    = (const float*)d_in[11];
    const float* Wk    = (const float*)d_in[12];
    const float* bk    = (const float*)d_in[13];
    const float* Wfc   = (const float*)d_in[14];
    const float* bfc   = (const float*)d_in[15];

    float* out_ctx   = (float*)d_out;                       // BS*ENC = 16384
    float* out_kappa = out_ctx + BS * ENC;                  // BS*HEADS = 256
    float* out_score = out_kappa + BS * HEADS;              // BS*SEQ*HEADS

    cudaMemsetAsync(d_out, 0, (size_t)out_size * sizeof(float), 0);

    k0_heads<<<BS, 128>>>(dec, kappa, Wb, bb, Wk, bk, out_kappa);
    k1_query<<<dim3(16, 8), 256>>>(dec, Wq, bq, bv);
    k2a_value<<<dim3(64, 4, BS), 256>>>(enc, Wv, Wf);
    k2b_score<<<BS, 128>>>(bf, mask, out_score);
    k3_ctx<<<BS, 256>>>(enc, out_score);
    k4_final<<<dim3(8, 8), 256>>>(Wfc, bfc, out_ctx);
}

// round 3
// speedup vs baseline: 1.8617x; 1.8617x over previous
#include <cuda_runtime.h>
#include <math.h>

#define BS    32
#define SEQ   2048
#define ENC   512
#define HEADS 8
#define IH    1024
#define DECIN 1024   // DEC + ENC

// ---------------- scratch (static device globals; no allocation) ----------------
__device__ float g_qv[BS][IH];              // dec@Wq + bq + bv
__device__ float g_beta[BS][HEADS];
__device__ float g_kap[BS][HEADS];
__device__ int   g_lo[BS];
__device__ int   g_hi[BS];
__device__ float g_pf[BS][4][SEQ][HEADS];   // partial h@Wf per j-tile
__device__ float g_ctx[BS][HEADS * ENC];    // context before Wfc

__device__ __forceinline__ float softplusf(float x) {
    // matches jax.nn.softplus = max(x,0) + log1p(exp(-|x|))
    return fmaxf(x, 0.f) + log1pf(expf(-fabsf(x)));
}

// ---------------- K0: heads projections (beta, kappa), active window ----------------
__global__ void k0_heads(const float* __restrict__ dec, const float* __restrict__ kappa_in,
                         const float* __restrict__ Wb, const float* __restrict__ bb,
                         const float* __restrict__ Wk, const float* __restrict__ bk,
                         float* __restrict__ out_kappa) {
    int b = blockIdx.x;
    __shared__ float sdec[DECIN];
    for (int i = threadIdx.x; i < DECIN; i += blockDim.x)
        sdec[i] = dec[b * DECIN + i];
    __syncthreads();
    __shared__ float sbeta[HEADS], skap[HEADS];
    int t = threadIdx.x;
    if (t < 16) {
        int h = t & 7;
        const float* W = (t < 8) ? Wb : Wk;
        float acc = 0.f;
        for (int k = 0; k < DECIN; k++) acc += sdec[k] * W[k * HEADS + h];
        if (t < 8) {
            float bv = softplusf(acc + bb[h]);
            sbeta[h] = bv;
            g_beta[b][h] = bv;
        } else {
            float kv = kappa_in[b * HEADS + h] + softplusf(acc + bk[h]);
            skap[h] = kv;
            g_kap[b][h] = kv;
            out_kappa[b * HEADS + h] = kv;
        }
    }
    __syncthreads();
    if (t == 0) {
        float lof = 1e30f, hif = -1e30f;
        for (int h = 0; h < HEADS; h++) {
            float R = sqrtf(110.f / sbeta[h]);   // outside: beta*d^2 > 110 -> expf == 0 exactly
            lof = fminf(lof, skap[h] - R);
            hif = fmaxf(hif, skap[h] + R);
        }
        int lo, hi;
        if (hif < 0.f || lof > (float)(SEQ - 1)) { lo = 0; hi = -1; }
        else {
            lo = (int)floorf(lof); if (lo < 0) lo = 0;
            hi = (int)ceilf(hif);  if (hi > SEQ - 1) hi = SEQ - 1;
        }
        g_lo[b] = lo; g_hi[b] = hi;
    }
}

// ---------------- K1: qv = dec@Wq + bq + bv ----------------
// grid (16 j-tiles of 64, 8 batch-groups of 4), block 256 = (c:64, ks:4)
__global__ void k1_query(const float* __restrict__ dec, const float* __restrict__ Wq,
                         const float* __restrict__ bq, const float* __restrict__ bv) {
    int jt = blockIdx.x, bg = blockIdx.y;
    int c  = threadIdx.x & 63;
    int ks = threadIdx.x >> 6;
    int j  = jt * 64 + c;
    __shared__ float sdec[4][DECIN];
    for (int i = threadIdx.x; i < 4 * DECIN; i += 256) {
        int bb = i >> 10, k = i & (DECIN - 1);
        sdec[bb][k] = dec[(bg * 4 + bb) * DECIN + k];
    }
    __syncthreads();
    float a0 = 0.f, a1 = 0.f, a2 = 0.f, a3 = 0.f;
    int k0 = ks * 256;
    #pragma unroll 4
    for (int k = k0; k < k0 + 256; k++) {
        float w = Wq[k * IH + j];
        a0 += sdec[0][k] * w; a1 += sdec[1][k] * w;
        a2 += sdec[2][k] * w; a3 += sdec[3][k] * w;
    }
    __shared__ float pacc[4][4][64];
    pacc[ks][0][c] = a0; pacc[ks][1][c] = a1;
    pacc[ks][2][c] = a2; pacc[ks][3][c] = a3;
    __syncthreads();
    if (ks == 0) {
        float add = bq[j] + bv[j];
        #pragma unroll
        for (int bb = 0; bb < 4; bb++) {
            float s = pacc[0][bb][c] + pacc[1][bb][c] + pacc[2][bb][c] + pacc[3][bb][c];
            g_qv[bg * 4 + bb][j] = s + add;
        }
    }
}

// ---------------- K2a: value slice GEMM + tanh + partial @Wf ----------------
// grid (128 row-chunks of 16, 4 j-tiles of 256, 32 batches), block 256 = (tx:32, ty:8)
// thread tile: 2 rows x 8 cols. Column mapping per thread: {tx*4+c} and {128+tx*4+c}
// (two float4 groups -> conflict-free LDS across the warp).
#define KK 16
__global__ void __launch_bounds__(256) k2a_value(const float* __restrict__ enc,
                                                 const float* __restrict__ Wv,
                                                 const float* __restrict__ Wf) {
    int chunk = blockIdx.x;
    int jt    = blockIdx.y;
    int b     = blockIdx.z;
    int lo = g_lo[b], hi = g_hi[b];
    int s0 = lo + chunk * 16;
    if (s0 > hi) return;
    int nrows = hi - s0 + 1; if (nrows > 16) nrows = 16;
    int jbase = jt * 256;
    int tx = threadIdx.x & 31;
    int ty = threadIdx.x >> 5;

    __shared__ float sWv[KK][256];
    __shared__ float sEnc[KK][18];

    float acc[2][8];
    #pragma unroll
    for (int r = 0; r < 2; r++)
        #pragma unroll
        for (int c = 0; c < 8; c++) acc[r][c] = 0.f;

    const float* encb = enc + (size_t)b * SEQ * ENC;

    // enc staging indices (one element per thread per k-tile)
    int er = threadIdx.x >> 4;      // 0..15 row
    int ek = threadIdx.x & 15;      // 0..15 k
    const float* encrow = encb + (size_t)(s0 + er) * ENC + ek;
    bool evalid = (er < nrows);

    for (int kk = 0; kk < ENC; kk += KK) {
        #pragma unroll
        for (int i = 0; i < 16; i++) {
            int idx = threadIdx.x + i * 256;
            int k = idx >> 8, jj = idx & 255;
            sWv[k][jj] = Wv[(size_t)(kk + k) * IH + jbase + jj];
        }
        sEnc[ek][er] = evalid ? encrow[kk] : 0.f;
        __syncthreads();
        #pragma unroll
        for (int k = 0; k < KK; k++) {
            float2 e  = *(const float2*)&sEnc[k][ty * 2];
            float4 w0 = *(const float4*)&sWv[k][tx * 4];
            float4 w1 = *(const float4*)&sWv[k][128 + tx * 4];
            float ev[2] = {e.x, e.y};
            float wv[8] = {w0.x, w0.y, w0.z, w0.w, w1.x, w1.y, w1.z, w1.w};
            #pragma unroll
            for (int r = 0; r < 2; r++)
                #pragma unroll
                for (int c = 0; c < 8; c++)
                    acc[r][c] += ev[r] * wv[c];
        }
        __syncthreads();
    }

    // epilogue: h = tanh(qv + value); pf[r][head] += h * Wf[j][head]
    float pf[2][8];
    #pragma unroll
    for (int r = 0; r < 2; r++)
        #pragma unroll
        for (int h = 0; h < 8; h++) pf[r][h] = 0.f;

    #pragma unroll
    for (int cc = 0; cc < 8; cc++) {
        int j = jbase + ((cc < 4) ? (tx * 4 + cc) : (128 + tx * 4 + (cc - 4)));
        float q = g_qv[b][j];
        float4 wa = *(const float4*)&Wf[j * 8];
        float4 wb = *(const float4*)&Wf[j * 8 + 4];
        float wf[8] = {wa.x, wa.y, wa.z, wa.w, wb.x, wb.y, wb.z, wb.w};
        #pragma unroll
        for (int r = 0; r < 2; r++) {
            float hv = tanhf(q + acc[r][cc]);
            #pragma unroll
            for (int h = 0; h < 8; h++) pf[r][h] += hv * wf[h];
        }
    }

    // deterministic warp butterfly reduction over tx (j within tile)
    #pragma unroll
    for (int r = 0; r < 2; r++)
        #pragma unroll
        for (int h = 0; h < 8; h++)
            #pragma unroll
            for (int off = 16; off >= 1; off >>= 1)
                pf[r][h] += __shfl_xor_sync(0xffffffffu, pf[r][h], off);

    if (tx == 0) {
        #pragma unroll
        for (int r = 0; r < 2; r++) {
            int lrow = ty * 2 + r;
            if (lrow < nrows) {
                int srel = chunk * 16 + lrow;
                #pragma unroll
                for (int h = 0; h < 8; h++)
                    g_pf[b][jt][srel][h] = pf[r][h];
            }
        }
    }
}

// ---------------- K2bc: combine partials -> score (smem) -> context ----------------
// grid (32 batches, 16 e-tiles of 32), block 256 = (e:32, h:8)
__global__ void __launch_bounds__(256) k2bc_score_ctx(const float* __restrict__ enc,
                                                      const float* __restrict__ bf,
                                                      const float* __restrict__ mask,
                                                      float* __restrict__ out_score) {
    int b  = blockIdx.x;
    int et = blockIdx.y;
    int lo = g_lo[b], hi = g_hi[b];
    int tx = threadIdx.x & 31;   // e within tile
    int h  = threadIdx.x >> 5;   // head
    int eg = et * 32 + tx;

    __shared__ float sc[256][8];
    float a0 = 0.f, a1 = 0.f, a2 = 0.f, a3 = 0.f;

    for (int st = lo; st <= hi; st += 256) {
        int tlen = hi - st + 1; if (tlen > 256) tlen = 256;
        __syncthreads();   // protect previous tile's sc reads
        for (int idx = threadIdx.x; idx < tlen * 8; idx += 256) {
            int sr = idx >> 3, hh = idx & 7;
            int s = st + sr;
            int srel = s - lo;
            float f = g_pf[b][0][srel][hh] + g_pf[b][1][srel][hh] +
                      g_pf[b][2][srel][hh] + g_pf[b][3][srel][hh] + bf[hh];
            float alpha = softplusf(f) * mask[b * SEQ + s];
            float d = g_kap[b][hh] - (float)s;
            float scv = alpha * expf(-g_beta[b][hh] * d * d);
            sc[sr][hh] = scv;
            if (et == 0)
                out_score[((size_t)b * SEQ + s) * HEADS + hh] = scv;
        }
        __syncthreads();
        const float* ep = enc + ((size_t)b * SEQ + st) * ENC + eg;
        int sr = 0;
        for (; sr + 4 <= tlen; sr += 4) {
            a0 += sc[sr + 0][h] * ep[(size_t)(sr + 0) * ENC];
            a1 += sc[sr + 1][h] * ep[(size_t)(sr + 1) * ENC];
            a2 += sc[sr + 2][h] * ep[(size_t)(sr + 2) * ENC];
            a3 += sc[sr + 3][h] * ep[(size_t)(sr + 3) * ENC];
        }
        for (; sr < tlen; sr++)
            a0 += sc[sr][h] * ep[(size_t)sr * ENC];
    }
    g_ctx[b][h * ENC + eg] = (a0 + a1) + (a2 + a3);
}

// ---------------- K4: context = context_raw @ Wfc + bfc ----------------
// grid (16 e-tiles of 32, 8 batch-groups of 4), block 256 = (e:32, js:8)
__global__ void __launch_bounds__(256) k4_final(const float* __restrict__ Wfc,
                                                const float* __restrict__ bfc,
                                                float* __restrict__ out_ctx) {
    int et = blockIdx.x, bg = blockIdx.y;
    int tx = threadIdx.x & 31;
    int js = threadIdx.x >> 5;
    int e  = et * 32 + tx;
    int j0 = js * 512;
    float a0 = 0.f, a1 = 0.f, a2 = 0.f, a3 = 0.f;
    const float* c0 = g_ctx[bg * 4 + 0];
    const float* c1 = g_ctx[bg * 4 + 1];
    const float* c2 = g_ctx[bg * 4 + 2];
    const float* c3 = g_ctx[bg * 4 + 3];
    #pragma unroll 8
    for (int j = j0; j < j0 + 512; j++) {
        float w = Wfc[(size_t)j * ENC + e];
        a0 += c0[j] * w;
        a1 += c1[j] * w;
        a2 += c2[j] * w;
        a3 += c3[j] * w;
    }
    __shared__ float red[8][4][32];
    red[js][0][tx] = a0; red[js][1][tx] = a1;
    red[js][2][tx] = a2; red[js][3][tx] = a3;
    __syncthreads();
    if (js < 4) {
        int bb = js;
        float s = 0.f;
        #pragma unroll
        for (int jj = 0; jj < 8; jj++) s += red[jj][bb][tx];
        out_ctx[(bg * 4 + bb) * ENC + e] = s + bfc[e];
    }
}

// ---------------- launch ----------------
extern "C" void kernel_launch(void* const* d_in, const int* in_sizes, int n_in,
                              void* d_out, int out_size) {
    const float* enc   = (const float*)d_in[0];
    const float* dec   = (const float*)d_in[1];
    const float* kappa = (const float*)d_in[2];
    const float* mask  = (const float*)d_in[3];
    const float* Wv    = (const float*)d_in[4];
    const float* bv    = (const float*)d_in[5];
    const float* Wq    = (const float*)d_in[6];
    const float* bq    = (const float*)d_in[7];
    const float* Wf    = (const float*)d_in[8];
    const float* bf    = (const float*)d_in[9];
    const float* Wb    = (const float*)d_in[10];
    const float* bb    = (const float*)d_in[11];
    const float* Wk    = (const float*)d_in[12];
    const float* bk    = (const float*)d_in[13];
    const float* Wfc   = (const float*)d_in[14];
    const float* bfc   = (const float*)d_in[15];

    float* out_ctx   = (float*)d_out;                       // BS*ENC
    float* out_kappa = out_ctx + BS * ENC;                  // BS*HEADS
    float* out_score = out_kappa + BS * HEADS;              // BS*SEQ*HEADS

    cudaMemsetAsync(out_score, 0, (size_t)BS * SEQ * HEADS * sizeof(float), 0);

    k0_heads<<<BS, 128>>>(dec, kappa, Wb, bb, Wk, bk, out_kappa);
    k1_query<<<dim3(16, 8), 256>>>(dec, Wq, bq, bv);
    k2a_value<<<dim3(128, 4, BS), 256>>>(enc, Wv, Wf);
    k2bc_score_ctx<<<dim3(BS, 16), 256>>>(enc, bf, mask, out_score);
    k4_final<<<dim3(16, 8), 256>>>(Wfc, bfc, out_ctx);
}

// round 6
// speedup vs baseline: 2.6572x; 1.4273x over previous
#include <cuda_runtime.h>
#include <math.h>

#define BS    32
#define SEQ   2048
#define ENC   512
#define HEADS 8
#define IH    1024
#define DECIN 1024   // DEC + ENC
#define ROWS_T 16
#define SENT  0xFFFFFFFFu

// ---------------- scratch (static device globals; no allocation) ----------------
__device__ float    g_qv[BS][IH];           // dec@Wq + bq + bv
__device__ float    g_beta[BS][HEADS];
__device__ float    g_kap[BS][HEADS];
__device__ int      g_lo[BS];
__device__ int      g_hi[BS];
__device__ unsigned g_rows[BS * SEQ];       // compacted (b<<16)|s
__device__ int      g_ntiles;
__device__ float    g_pf[BS][SEQ][64];      // partials: [b][s][jt*8+h]
__device__ float    g_ctx[BS][HEADS * ENC]; // context before Wfc

__device__ __forceinline__ float softplusf(float x) {
    // matches jax.nn.softplus = max(x,0) + log1p(exp(-|x|))
    return fmaxf(x, 0.f) + log1pf(expf(-fabsf(x)));
}

// ---------------- K0: heads projections (beta, kappa), active window ----------------
__global__ void k0_heads(const float* __restrict__ dec, const float* __restrict__ kappa_in,
                         const float* __restrict__ Wb, const float* __restrict__ bb,
                         const float* __restrict__ Wk, const float* __restrict__ bk,
                         float* __restrict__ out_kappa) {
    int b = blockIdx.x;
    __shared__ float sdec[DECIN];
    for (int i = threadIdx.x; i < DECIN; i += blockDim.x)
        sdec[i] = dec[b * DECIN + i];
    __syncthreads();
    __shared__ float sbeta[HEADS], skap[HEADS];
    int t = threadIdx.x;
    if (t < 16) {
        int h = t & 7;
        const float* W = (t < 8) ? Wb : Wk;
        float acc = 0.f;
        for (int k = 0; k < DECIN; k++) acc += sdec[k] * W[k * HEADS + h];
        if (t < 8) {
            float bv2 = softplusf(acc + bb[h]);
            sbeta[h] = bv2;
            g_beta[b][h] = bv2;
        } else {
            float kv = kappa_in[b * HEADS + h] + softplusf(acc + bk[h]);
            skap[h] = kv;
            g_kap[b][h] = kv;
            out_kappa[b * HEADS + h] = kv;
        }
    }
    __syncthreads();
    if (t == 0) {
        float lof = 1e30f, hif = -1e30f;
        for (int h = 0; h < HEADS; h++) {
            float R = sqrtf(110.f / sbeta[h]);   // outside: beta*d^2 > 110 -> expf == 0 exactly
            lof = fminf(lof, skap[h] - R);
            hif = fmaxf(hif, skap[h] + R);
        }
        int lo, hi;
        if (hif < 0.f || lof > (float)(SEQ - 1)) { lo = 0; hi = -1; }
        else {
            lo = (int)floorf(lof); if (lo < 0) lo = 0;
            hi = (int)ceilf(hif);  if (hi > SEQ - 1) hi = SEQ - 1;
        }
        g_lo[b] = lo; g_hi[b] = hi;
    }
}

// ---------------- K0b: compact active rows across batches ----------------
__global__ void k0b_compact() {
    __shared__ int soff[BS + 1];
    int t = threadIdx.x;
    if (t == 0) {
        int off = 0;
        for (int b = 0; b < BS; b++) {
            soff[b] = off;
            int w = g_hi[b] - g_lo[b] + 1;
            if (w < 0) w = 0;
            off += w;
        }
        soff[BS] = off;
        int nt = (off + ROWS_T - 1) / ROWS_T;
        if (nt < 1) nt = 1;
        g_ntiles = nt;
    }
    __syncthreads();
    int total = soff[BS];
    int padded = ((total + ROWS_T - 1) / ROWS_T) * ROWS_T;
    if (padded < ROWS_T) padded = ROWS_T;
    for (int b = 0; b < BS; b++) {
        int lo = g_lo[b];
        int w  = soff[b + 1] - soff[b];
        int base = soff[b];
        for (int i = t; i < w; i += blockDim.x)
            g_rows[base + i] = ((unsigned)b << 16) | (unsigned)(lo + i);
    }
    for (int i = total + t; i < padded; i += blockDim.x)
        g_rows[i] = SENT;
}

// ---------------- K1: qv = dec@Wq + bq + bv ----------------
__global__ void k1_query(const float* __restrict__ dec, const float* __restrict__ Wq,
                         const float* __restrict__ bq, const float* __restrict__ bv) {
    int jt = blockIdx.x, bg = blockIdx.y;
    int c  = threadIdx.x & 63;
    int ks = threadIdx.x >> 6;
    int j  = jt * 64 + c;
    __shared__ float sdec[4][DECIN];
    for (int i = threadIdx.x; i < 4 * DECIN; i += 256) {
        int bb = i >> 10, k = i & (DECIN - 1);
        sdec[bb][k] = dec[(bg * 4 + bb) * DECIN + k];
    }
    __syncthreads();
    float a0 = 0.f, a1 = 0.f, a2 = 0.f, a3 = 0.f;
    int k0 = ks * 256;
    #pragma unroll 4
    for (int k = k0; k < k0 + 256; k++) {
        float w = Wq[k * IH + j];
        a0 += sdec[0][k] * w; a1 += sdec[1][k] * w;
        a2 += sdec[2][k] * w; a3 += sdec[3][k] * w;
    }
    __shared__ float pacc[4][4][64];
    pacc[ks][0][c] = a0; pacc[ks][1][c] = a1;
    pacc[ks][2][c] = a2; pacc[ks][3][c] = a3;
    __syncthreads();
    if (ks == 0) {
        float add = bq[j] + bv[j];
        #pragma unroll
        for (int bb = 0; bb < 4; bb++) {
            float s = pacc[0][bb][c] + pacc[1][bb][c] + pacc[2][bb][c] + pacc[3][bb][c];
            g_qv[bg * 4 + bb][j] = s + add;
        }
    }
}

// ---------------- K2a: compacted value GEMM + tanh + partial @Wf ----------------
// grid (64, 8 j-tiles of 128), block 256 = (tx:32, ty:8); thread tile 2 rows x 4 cols.
#define KK2 32
__global__ void __launch_bounds__(256) k2a_value(const float* __restrict__ enc,
                                                 const float* __restrict__ Wv,
                                                 const float* __restrict__ Wf) {
    int jt    = blockIdx.y;
    int jbase = jt * 128;
    int tx = threadIdx.x & 31;
    int ty = threadIdx.x >> 5;
    int ntiles = g_ntiles;

    __shared__ float    sWv[KK2][128];
    __shared__ float    sEnc[ROWS_T][KK2];
    __shared__ unsigned smeta[ROWS_T];

    for (int t = blockIdx.x; t < ntiles; t += gridDim.x) {
        if (t != (int)blockIdx.x) __syncthreads();
        if (threadIdx.x < ROWS_T) smeta[threadIdx.x] = g_rows[t * ROWS_T + threadIdx.x];
        __syncthreads();

        // staging rows for this thread: rows ty and ty+8, k = tx
        unsigned ma = smeta[ty], mb = smeta[ty + 8];
        const float* pa = (ma != SENT)
            ? enc + ((size_t)(ma >> 16) * SEQ + (ma & 0xFFFF)) * ENC + tx : (const float*)0;
        const float* pb = (mb != SENT)
            ? enc + ((size_t)(mb >> 16) * SEQ + (mb & 0xFFFF)) * ENC + tx : (const float*)0;

        float acc[2][4];
        #pragma unroll
        for (int r = 0; r < 2; r++)
            #pragma unroll
            for (int c = 0; c < 4; c++) acc[r][c] = 0.f;

        for (int kk = 0; kk < ENC; kk += KK2) {
            #pragma unroll
            for (int i = 0; i < 16; i++) {
                int idx = (int)threadIdx.x + i * 256;
                int k = idx >> 7, jj = idx & 127;
                sWv[k][jj] = Wv[(size_t)(kk + k) * IH + jbase + jj];
            }
            sEnc[ty][tx]     = pa ? pa[kk] : 0.f;
            sEnc[ty + 8][tx] = pb ? pb[kk] : 0.f;
            __syncthreads();
            #pragma unroll
            for (int k = 0; k < KK2; k++) {
                float4 w = *(const float4*)&sWv[k][tx * 4];
                float e0 = sEnc[2 * ty][k];
                float e1 = sEnc[2 * ty + 1][k];
                acc[0][0] += e0 * w.x; acc[0][1] += e0 * w.y;
                acc[0][2] += e0 * w.z; acc[0][3] += e0 * w.w;
                acc[1][0] += e1 * w.x; acc[1][1] += e1 * w.y;
                acc[1][2] += e1 * w.z; acc[1][3] += e1 * w.w;
            }
            __syncthreads();
        }

        // epilogue rows for this thread: 2*ty, 2*ty+1
        unsigned m0 = smeta[2 * ty], m1 = smeta[2 * ty + 1];
        float pf[2][8];
        #pragma unroll
        for (int r = 0; r < 2; r++)
            #pragma unroll
            for (int h = 0; h < 8; h++) pf[r][h] = 0.f;

        #pragma unroll
        for (int cc = 0; cc < 4; cc++) {
            int j = jbase + tx * 4 + cc;
            float q0 = (m0 != SENT) ? g_qv[m0 >> 16][j] : 0.f;
            float q1 = (m1 != SENT) ? g_qv[m1 >> 16][j] : 0.f;
            float4 wa = *(const float4*)&Wf[j * 8];
            float4 wb = *(const float4*)&Wf[j * 8 + 4];
            float h0 = tanhf(q0 + acc[0][cc]);
            float h1 = tanhf(q1 + acc[1][cc]);
            pf[0][0] += h0 * wa.x; pf[0][1] += h0 * wa.y;
            pf[0][2] += h0 * wa.z; pf[0][3] += h0 * wa.w;
            pf[0][4] += h0 * wb.x; pf[0][5] += h0 * wb.y;
            pf[0][6] += h0 * wb.z; pf[0][7] += h0 * wb.w;
            pf[1][0] += h1 * wa.x; pf[1][1] += h1 * wa.y;
            pf[1][2] += h1 * wa.z; pf[1][3] += h1 * wa.w;
            pf[1][4] += h1 * wb.x; pf[1][5] += h1 * wb.y;
            pf[1][6] += h1 * wb.z; pf[1][7] += h1 * wb.w;
        }

        // deterministic warp butterfly reduction over tx (j within tile)
        #pragma unroll
        for (int r = 0; r < 2; r++)
            #pragma unroll
            for (int h = 0; h < 8; h++)
                #pragma unroll
                for (int off = 16; off >= 1; off >>= 1)
                    pf[r][h] += __shfl_xor_sync(0xffffffffu, pf[r][h], off);

        if (tx == 0) {
            if (m0 != SENT) {
                float* dst = &g_pf[m0 >> 16][m0 & 0xFFFF][jt * 8];
                *(float4*)dst       = make_float4(pf[0][0], pf[0][1], pf[0][2], pf[0][3]);
                *(float4*)(dst + 4) = make_float4(pf[0][4], pf[0][5], pf[0][6], pf[0][7]);
            }
            if (m1 != SENT) {
                float* dst = &g_pf[m1 >> 16][m1 & 0xFFFF][jt * 8];
                *(float4*)dst       = make_float4(pf[1][0], pf[1][1], pf[1][2], pf[1][3]);
                *(float4*)(dst + 4) = make_float4(pf[1][4], pf[1][5], pf[1][6], pf[1][7]);
            }
        }
    }
}

// ---------------- K2bc: combine partials -> score (smem) -> context ----------------
// grid (32 batches, 16 e-tiles of 32), block 256 = (e:32, h:8)
__global__ void __launch_bounds__(256) k2bc_score_ctx(const float* __restrict__ enc,
                                                      const float* __restrict__ bf,
                                                      const float* __restrict__ mask,
                                                      float* __restrict__ out_score) {
    int b  = blockIdx.x;
    int et = blockIdx.y;
    int lo = g_lo[b], hi = g_hi[b];
    int tx = threadIdx.x & 31;   // e within tile
    int h  = threadIdx.x >> 5;   // head
    int eg = et * 32 + tx;

    __shared__ float sc[256][8];
    float a0 = 0.f, a1 = 0.f, a2 = 0.f, a3 = 0.f;

    for (int st = lo; st <= hi; st += 256) {
        int tlen = hi - st + 1; if (tlen > 256) tlen = 256;
        __syncthreads();
        for (int idx = threadIdx.x; idx < tlen * 8; idx += 256) {
            int sr = idx >> 3, hh = idx & 7;
            int s = st + sr;
            const float* p = g_pf[b][s];
            float f = bf[hh];
            #pragma unroll
            for (int pp = 0; pp < 8; pp++) f += p[pp * 8 + hh];
            float alpha = softplusf(f) * mask[b * SEQ + s];
            float d = g_kap[b][hh] - (float)s;
            float scv = alpha * expf(-g_beta[b][hh] * d * d);
            sc[sr][hh] = scv;
            if (et == 0)
                out_score[((size_t)b * SEQ + s) * HEADS + hh] = scv;
        }
        __syncthreads();
        const float* ep = enc + ((size_t)b * SEQ + st) * ENC + eg;
        int sr = 0;
        for (; sr + 4 <= tlen; sr += 4) {
            a0 += sc[sr + 0][h] * ep[(size_t)(sr + 0) * ENC];
            a1 += sc[sr + 1][h] * ep[(size_t)(sr + 1) * ENC];
            a2 += sc[sr + 2][h] * ep[(size_t)(sr + 2) * ENC];
            a3 += sc[sr + 3][h] * ep[(size_t)(sr + 3) * ENC];
        }
        for (; sr < tlen; sr++)
            a0 += sc[sr][h] * ep[(size_t)sr * ENC];
    }
    g_ctx[b][h * ENC + eg] = (a0 + a1) + (a2 + a3);
}

// ---------------- K4: context = context_raw @ Wfc + bfc ----------------
__global__ void __launch_bounds__(256) k4_final(const float* __restrict__ Wfc,
                                                const float* __restrict__ bfc,
                                                float* __restrict__ out_ctx) {
    int et = blockIdx.x, bg = blockIdx.y;
    int tx = threadIdx.x & 31;
    int js = threadIdx.x >> 5;
    int e  = et * 32 + tx;
    int j0 = js * 512;
    float a0 = 0.f, a1 = 0.f, a2 = 0.f, a3 = 0.f;
    const float* c0 = g_ctx[bg * 4 + 0];
    const float* c1 = g_ctx[bg * 4 + 1];
    const float* c2 = g_ctx[bg * 4 + 2];
    const float* c3 = g_ctx[bg * 4 + 3];
    #pragma unroll 8
    for (int j = j0; j < j0 + 512; j++) {
        float w = Wfc[(size_t)j * ENC + e];
        a0 += c0[j] * w;
        a1 += c1[j] * w;
        a2 += c2[j] * w;
        a3 += c3[j] * w;
    }
    __shared__ float red[8][4][32];
    red[js][0][tx] = a0; red[js][1][tx] = a1;
    red[js][2][tx] = a2; red[js][3][tx] = a3;
    __syncthreads();
    if (js < 4) {
        int bb = js;
        float s = 0.f;
        #pragma unroll
        for (int jj = 0; jj < 8; jj++) s += red[jj][bb][tx];
        out_ctx[(bg * 4 + bb) * ENC + e] = s + bfc[e];
    }
}

// ---------------- launch ----------------
extern "C" void kernel_launch(void* const* d_in, const int* in_sizes, int n_in,
                              void* d_out, int out_size) {
    const float* enc   = (const float*)d_in[0];
    const float* dec   = (const float*)d_in[1];
    const float* kappa = (const float*)d_in[2];
    const float* mask  = (const float*)d_in[3];
    const float* Wv    = (const float*)d_in[4];
    const float* bv    = (const float*)d_in[5];
    const float* Wq    = (const float*)d_in[6];
    const float* bq    = (const float*)d_in[7];
    const float* Wf    = (const float*)d_in[8];
    const float* bf    = (const float*)d_in[9];
    const float* Wb    = (const float*)d_in[10];
    const float* bb    = (const float*)d_in[11];
    const float* Wk    = (const float*)d_in[12];
    const float* bk    = (const float*)d_in[13];
    const float* Wfc   = (const float*)d_in[14];
    const float* bfc   = (const float*)d_in[15];

    float* out_ctx   = (float*)d_out;                       // BS*ENC
    float* out_kappa = out_ctx + BS * ENC;                  // BS*HEADS
    float* out_score = out_kappa + BS * HEADS;              // BS*SEQ*HEADS

    cudaMemsetAsync(out_score, 0, (size_t)BS * SEQ * HEADS * sizeof(float), 0);

    k0_heads<<<BS, 128>>>(dec, kappa, Wb, bb, Wk, bk, out_kappa);
    k0b_compact<<<1, 256>>>();
    k1_query<<<dim3(16, 8), 256>>>(dec, Wq, bq, bv);
    k2a_value<<<dim3(64, 8), 256>>>(enc, Wv, Wf);
    k2bc_score_ctx<<<dim3(BS, 16), 256>>>(enc, bf, mask, out_score);
    k4_final<<<dim3(16, 8), 256>>>(Wfc, bfc, out_ctx);
}

// round 8
// speedup vs baseline: 2.9293x; 1.1024x over previous
#include <cuda_runtime.h>
#include <cuda_bf16.h>
#include <math.h>
#include <stdint.h>

#define BS    32
#define SEQ   2048
#define ENC   512
#define HEADS 8
#define IH    1024
#define DECIN 1024
#define SENT  0xFFFFFFFFu

#define MT 128           // rows per m-tile
#define NT 64            // j per n-tile
#define NJT (IH / NT)    // 16 n-tiles
#define KC 64            // K chunk (bf16 -> 128B rows, SW128)
#define MAXTILES 512     // max m-tiles (BS*SEQ/128)

// ---------------- scratch ----------------
__device__ float         g_qv[BS][IH];
__device__ float         g_beta[BS][HEADS];
__device__ float         g_kap[BS][HEADS];
__device__ int           g_lo[BS];
__device__ int           g_hi[BS];
__device__ unsigned      g_rows[BS * SEQ + MT];
__device__ int           g_nt128;
__device__ float         g_pf[BS][SEQ][NJT * HEADS];   // [b][s][jt*8+h]
__device__ float         g_ctx[BS][HEADS * ENC];
__device__ __nv_bfloat16 g_WvThi[IH * ENC];            // [j][k]
__device__ __nv_bfloat16 g_WvTlo[IH * ENC];
__device__ __nv_bfloat16 g_Ahi[(size_t)MAXTILES * MT * ENC];  // compacted enc rows
__device__ __nv_bfloat16 g_Alo[(size_t)MAXTILES * MT * ENC];

__device__ __forceinline__ float softplusf(float x) {
    return fmaxf(x, 0.f) + log1pf(expf(-fabsf(x)));
}

#define SW128(x) ((x) ^ (((x) >> 3) & 0x70))

__device__ __forceinline__ uint32_t smem_u32(const void* p) {
    uint32_t a;
    asm("{ .reg .u64 t; cvta.to.shared.u64 t, %1; cvt.u32.u64 %0, t; }" : "=r"(a) : "l"(p));
    return a;
}
__device__ __forceinline__ void ldsm4(uint32_t* r, uint32_t addr) {
    asm volatile("ldmatrix.sync.aligned.m8n8.x4.shared.b16 {%0,%1,%2,%3}, [%4];"
                 : "=r"(r[0]), "=r"(r[1]), "=r"(r[2]), "=r"(r[3]) : "r"(addr));
}
__device__ __forceinline__ void mma16816(float* c, const uint32_t* a,
                                         uint32_t b0, uint32_t b1) {
    asm volatile("mma.sync.aligned.m16n8k16.row.col.f32.bf16.bf16.f32 "
                 "{%0,%1,%2,%3}, {%4,%5,%6,%7}, {%8,%9}, {%0,%1,%2,%3};"
                 : "+f"(c[0]), "+f"(c[1]), "+f"(c[2]), "+f"(c[3])
                 : "r"(a[0]), "r"(a[1]), "r"(a[2]), "r"(a[3]), "r"(b0), "r"(b1));
}

// ---------------- K0: heads projections + active window ----------------
__global__ void k0_heads(const float* __restrict__ dec, const float* __restrict__ kappa_in,
                         const float* __restrict__ Wb, const float* __restrict__ bb,
                         const float* __restrict__ Wk, const float* __restrict__ bk,
                         float* __restrict__ out_kappa) {
    int b = blockIdx.x;
    __shared__ float sdec[DECIN];
    for (int i = threadIdx.x; i < DECIN; i += blockDim.x)
        sdec[i] = dec[b * DECIN + i];
    __syncthreads();
    __shared__ float sbeta[HEADS], skap[HEADS];
    int w = threadIdx.x >> 5, lane = threadIdx.x & 31;
    if (w < 16) {
        int h = w & 7;
        const float* W = (w < 8) ? Wb : Wk;
        float acc = 0.f;
        for (int k = lane; k < DECIN; k += 32) acc += sdec[k] * W[k * HEADS + h];
        #pragma unroll
        for (int off = 16; off >= 1; off >>= 1)
            acc += __shfl_xor_sync(0xffffffffu, acc, off);
        if (lane == 0) {
            if (w < 8) {
                float bv2 = softplusf(acc + bb[h]);
                sbeta[h] = bv2;
                g_beta[b][h] = bv2;
            } else {
                float kv = kappa_in[b * HEADS + h] + softplusf(acc + bk[h]);
                skap[h] = kv;
                g_kap[b][h] = kv;
                out_kappa[b * HEADS + h] = kv;
            }
        }
    }
    __syncthreads();
    if (threadIdx.x == 0) {
        float lof = 1e30f, hif = -1e30f;
        for (int h = 0; h < HEADS; h++) {
            float R = sqrtf(110.f / sbeta[h]);
            lof = fminf(lof, skap[h] - R);
            hif = fmaxf(hif, skap[h] + R);
        }
        int lo, hi;
        if (hif < 0.f || lof > (float)(SEQ - 1)) { lo = 0; hi = -1; }
        else {
            lo = (int)floorf(lof); if (lo < 0) lo = 0;
            hi = (int)ceilf(hif);  if (hi > SEQ - 1) hi = SEQ - 1;
        }
        g_lo[b] = lo; g_hi[b] = hi;
    }
}

// ---------------- K0b: compact active rows (pad to 128) ----------------
__global__ void k0b_compact() {
    __shared__ int soff[BS + 1];
    int t = threadIdx.x;
    if (t == 0) {
        int off = 0;
        for (int b = 0; b < BS; b++) {
            soff[b] = off;
            int w = g_hi[b] - g_lo[b] + 1;
            if (w < 0) w = 0;
            off += w;
        }
        soff[BS] = off;
        int nt = (off + MT - 1) / MT;
        if (nt < 1) nt = 1;
        g_nt128 = nt;
    }
    __syncthreads();
    int total = soff[BS];
    int padded = ((total + MT - 1) / MT) * MT;
    if (padded < MT) padded = MT;
    for (int b = 0; b < BS; b++) {
        int lo = g_lo[b];
        int w  = soff[b + 1] - soff[b];
        int base = soff[b];
        for (int i = t; i < w; i += blockDim.x)
            g_rows[base + i] = ((unsigned)b << 16) | (unsigned)(lo + i);
    }
    for (int i = total + t; i < padded; i += blockDim.x)
        g_rows[i] = SENT;
}

// ---------------- kE: split compacted enc rows into bf16 hi/lo ----------------
// grid 512 (one block per m-tile, early exit), block 256: row=tid>>1, half=tid&1
__global__ void kE_split(const float* __restrict__ enc) {
    int tile = blockIdx.x;
    if (tile >= g_nt128) return;
    int row  = threadIdx.x >> 1;
    int half = threadIdx.x & 1;
    int grow = tile * MT + row;
    unsigned m = g_rows[grow];
    size_t dbase = (size_t)grow * ENC + half * 256;
    if (m == SENT) {
        uint4 z = make_uint4(0, 0, 0, 0);
        #pragma unroll 8
        for (int q = 0; q < 32; q++) {
            ((uint4*)(g_Ahi + dbase))[q] = z;
            ((uint4*)(g_Alo + dbase))[q] = z;
        }
        return;
    }
    const float4* src = (const float4*)(enc + ((size_t)(m >> 16) * SEQ + (m & 0xFFFF)) * ENC
                                        + half * 256);
    #pragma unroll 4
    for (int q = 0; q < 32; q++) {
        float4 v0 = src[q * 2], v1 = src[q * 2 + 1];
        float x[8] = {v0.x, v0.y, v0.z, v0.w, v1.x, v1.y, v1.z, v1.w};
        __nv_bfloat16 hi[8], lo[8];
        #pragma unroll
        for (int i = 0; i < 8; i++) {
            hi[i] = __float2bfloat16(x[i]);
            lo[i] = __float2bfloat16(x[i] - __bfloat162float(hi[i]));
        }
        ((uint4*)(g_Ahi + dbase))[q] = *(const uint4*)hi;
        ((uint4*)(g_Alo + dbase))[q] = *(const uint4*)lo;
    }
}

// ---------------- kW: split Wv into bf16 hi/lo, transposed [j][k] ----------------
__global__ void kW_split(const float* __restrict__ Wv) {
    __shared__ float s[32][33];
    int k0 = blockIdx.x * 32, j0 = blockIdx.y * 32;
    int jl = threadIdx.x & 31, kq = threadIdx.x >> 5;
    #pragma unroll
    for (int i = 0; i < 4; i++)
        s[kq * 4 + i][jl] = Wv[(size_t)(k0 + kq * 4 + i) * IH + j0 + jl];
    __syncthreads();
    int jr = threadIdx.x >> 3;
    int kg = (threadIdx.x & 7) * 4;
    __nv_bfloat16 hi[4], lo[4];
    #pragma unroll
    for (int i = 0; i < 4; i++) {
        float x = s[kg + i][jr];
        hi[i] = __float2bfloat16(x);
        lo[i] = __float2bfloat16(x - __bfloat162float(hi[i]));
    }
    size_t dst = (size_t)(j0 + jr) * ENC + k0 + kg;
    *(uint2*)(g_WvThi + dst) = *(const uint2*)hi;
    *(uint2*)(g_WvTlo + dst) = *(const uint2*)lo;
}

// ---------------- K1: qv = dec@Wq + bq + bv ----------------
__global__ void k1_query(const float* __restrict__ dec, const float* __restrict__ Wq,
                         const float* __restrict__ bq, const float* __restrict__ bv) {
    int jt = blockIdx.x, bg = blockIdx.y;
    int c  = threadIdx.x & 63;
    int ks = threadIdx.x >> 6;
    int j  = jt * 64 + c;
    __shared__ float sdec[4][DECIN];
    for (int i = threadIdx.x; i < 4 * DECIN; i += 256) {
        int bb = i >> 10, k = i & (DECIN - 1);
        sdec[bb][k] = dec[(bg * 4 + bb) * DECIN + k];
    }
    __syncthreads();
    float a0 = 0.f, a1 = 0.f, a2 = 0.f, a3 = 0.f;
    int k0 = ks * 256;
    #pragma unroll 4
    for (int k = k0; k < k0 + 256; k++) {
        float w = Wq[k * IH + j];
        a0 += sdec[0][k] * w; a1 += sdec[1][k] * w;
        a2 += sdec[2][k] * w; a3 += sdec[3][k] * w;
    }
    __shared__ float pacc[4][4][64];
    pacc[ks][0][c] = a0; pacc[ks][1][c] = a1;
    pacc[ks][2][c] = a2; pacc[ks][3][c] = a3;
    __syncthreads();
    if (ks == 0) {
        float add = bq[j] + bv[j];
        #pragma unroll
        for (int bb = 0; bb < 4; bb++) {
            float s = pacc[0][bb][c] + pacc[1][bb][c] + pacc[2][bb][c] + pacc[3][bb][c];
            g_qv[bg * 4 + bb][j] = s + add;
        }
    }
}

// ---------------- K2a: warp-MMA bf16-split value GEMM + tanh + partial @Wf ----------------
// block 256 (8 warps). tile: 128 rows x 64 j. Each warp: 16 rows x 64 j.
#define OFF_A_HI 0
#define OFF_A_LO 16384
#define OFF_B_HI 32768
#define OFF_B_LO 40960
#define OFF_WF   49152
#define OFF_META 51200
#define SMEM_DYN (51712 + 1024)

__global__ void __launch_bounds__(256) k2a_mma(const float* __restrict__ Wf) {
    int nt = g_nt128;
    int total_tiles = nt * NJT;

    extern __shared__ char dsm[];
    uint32_t b0 = smem_u32(dsm);
    uint32_t ab = (b0 + 1023u) & ~1023u;
    char* dyn = dsm + (ab - b0);
    float*    sWf   = (float*)(dyn + OFF_WF);
    unsigned* smeta = (unsigned*)(dyn + OFF_META);

    int tid  = threadIdx.x;
    int wid  = tid >> 5, lane = tid & 31;

    // ldmatrix lane address components (byte offsets within tile, pre-swizzle)
    int wm = wid * 16;
    uint32_t a_rb   = (uint32_t)((wm + (lane & 15)) * 128 + ((lane & 16) ? 16 : 0));
    uint32_t a_msk  = (a_rb >> 3) & 0x70;
    uint32_t b_rb[4], b_msk[4];
    #pragma unroll
    for (int p = 0; p < 4; p++) {
        int n = p * 16 + (lane & 7) + ((lane & 16) ? 8 : 0);
        b_rb[p]  = (uint32_t)(n * 128 + ((lane & 8) ? 16 : 0));
        b_msk[p] = (b_rb[p] >> 3) & 0x70;
    }
    uint32_t Ahi_b = ab + OFF_A_HI, Alo_b = ab + OFF_A_LO;
    uint32_t Bhi_b = ab + OFF_B_HI, Blo_b = ab + OFF_B_LO;

    // staging mapping
    int srow = tid >> 1, shalf = tid & 1;    // A: 128 rows x 2 halves
    int bn   = tid >> 2, bq = (tid & 3) * 2; // B: 64 rows x 4 quarter-pairs

    for (int t = blockIdx.x; t < total_tiles; t += gridDim.x) {
        int mtile = t >> 4;
        int jt    = t & 15;
        int jbase = jt * NT;

        __syncthreads();   // previous iteration's epilogue reads done
        if (tid < MT) smeta[tid] = g_rows[mtile * MT + tid];
        for (int i = tid; i < NT * 8; i += 256) sWf[i] = Wf[jbase * 8 + i];

        float acc[8][4];
        #pragma unroll
        for (int nf = 0; nf < 8; nf++)
            #pragma unroll
            for (int q = 0; q < 4; q++) acc[nf][q] = 0.f;

        const uint4* Ah_src = (const uint4*)(g_Ahi + ((size_t)(mtile * MT + srow)) * ENC);
        const uint4* Al_src = (const uint4*)(g_Alo + ((size_t)(mtile * MT + srow)) * ENC);
        const uint4* Bh_src = (const uint4*)(g_WvThi + (size_t)(jbase + bn) * ENC);
        const uint4* Bl_src = (const uint4*)(g_WvTlo + (size_t)(jbase + bn) * ENC);

        for (int kc = 0; kc < ENC / KC; kc++) {
            int kk8 = kc * (KC / 8);   // uint4 index base within row
            __syncthreads();
            // stage A (hi/lo): 4 uint4 per matrix per thread
            #pragma unroll
            for (int q = 0; q < 4; q++) {
                uint32_t o = SW128((uint32_t)(srow * 128 + shalf * 64 + q * 16));
                *(uint4*)(dyn + OFF_A_HI + o) = Ah_src[kk8 + shalf * 4 + q];
                *(uint4*)(dyn + OFF_A_LO + o) = Al_src[kk8 + shalf * 4 + q];
            }
            // stage B (hi/lo): 2 uint4 per matrix per thread
            #pragma unroll
            for (int q = 0; q < 2; q++) {
                uint32_t o = SW128((uint32_t)(bn * 128 + (bq + q) * 16));
                *(uint4*)(dyn + OFF_B_HI + o) = Bh_src[kk8 + bq + q];
                *(uint4*)(dyn + OFF_B_LO + o) = Bl_src[kk8 + bq + q];
            }
            __syncthreads();
            #pragma unroll
            for (int ks = 0; ks < 4; ks++) {
                uint32_t ah[4], al[4];
                ldsm4(ah, Ahi_b + ((a_rb + ks * 32) ^ a_msk));
                ldsm4(al, Alo_b + ((a_rb + ks * 32) ^ a_msk));
                #pragma unroll
                for (int p = 0; p < 4; p++) {
                    uint32_t bh[4], bl[4];
                    ldsm4(bh, Bhi_b + ((b_rb[p] + ks * 32) ^ b_msk[p]));
                    ldsm4(bl, Blo_b + ((b_rb[p] + ks * 32) ^ b_msk[p]));
                    mma16816(acc[p * 2],     ah, bh[0], bh[1]);
                    mma16816(acc[p * 2],     ah, bl[0], bl[1]);
                    mma16816(acc[p * 2],     al, bh[0], bh[1]);
                    mma16816(acc[p * 2 + 1], ah, bh[2], bh[3]);
                    mma16816(acc[p * 2 + 1], ah, bl[2], bl[3]);
                    mma16816(acc[p * 2 + 1], al, bh[2], bh[3]);
                }
            }
        }

        // ---- epilogue ----
        int r0 = wm + (lane >> 2);
        int r1 = r0 + 8;
        unsigned m0 = smeta[r0], m1 = smeta[r1];
        const float* qv0 = &g_qv[(m0 != SENT) ? (m0 >> 16) : 0][jbase];
        const float* qv1 = &g_qv[(m1 != SENT) ? (m1 >> 16) : 0][jbase];
        float pf0[8], pf1[8];
        #pragma unroll
        for (int h = 0; h < 8; h++) { pf0[h] = 0.f; pf1[h] = 0.f; }
        #pragma unroll
        for (int nf = 0; nf < 8; nf++) {
            int jl = nf * 8 + 2 * (lane & 3);
            float hv00 = (m0 != SENT) ? tanhf(qv0[jl]     + acc[nf][0]) : 0.f;
            float hv01 = (m0 != SENT) ? tanhf(qv0[jl + 1] + acc[nf][1]) : 0.f;
            float hv10 = (m1 != SENT) ? tanhf(qv1[jl]     + acc[nf][2]) : 0.f;
            float hv11 = (m1 != SENT) ? tanhf(qv1[jl + 1] + acc[nf][3]) : 0.f;
            const float* w0 = &sWf[jl * 8];
            const float* w1 = &sWf[(jl + 1) * 8];
            #pragma unroll
            for (int h = 0; h < 8; h++) {
                pf0[h] += hv00 * w0[h] + hv01 * w1[h];
                pf1[h] += hv10 * w0[h] + hv11 * w1[h];
            }
        }
        #pragma unroll
        for (int h = 0; h < 8; h++) {
            pf0[h] += __shfl_xor_sync(0xffffffffu, pf0[h], 1);
            pf0[h] += __shfl_xor_sync(0xffffffffu, pf0[h], 2);
            pf1[h] += __shfl_xor_sync(0xffffffffu, pf1[h], 1);
            pf1[h] += __shfl_xor_sync(0xffffffffu, pf1[h], 2);
        }
        if ((lane & 3) == 0) {
            if (m0 != SENT) {
                float* dst = &g_pf[m0 >> 16][m0 & 0xFFFF][jt * 8];
                *(float4*)dst       = make_float4(pf0[0], pf0[1], pf0[2], pf0[3]);
                *(float4*)(dst + 4) = make_float4(pf0[4], pf0[5], pf0[6], pf0[7]);
            }
            if (m1 != SENT) {
                float* dst = &g_pf[m1 >> 16][m1 & 0xFFFF][jt * 8];
                *(float4*)dst       = make_float4(pf1[0], pf1[1], pf1[2], pf1[3]);
                *(float4*)(dst + 4) = make_float4(pf1[4], pf1[5], pf1[6], pf1[7]);
            }
        }
    }
}

// ---------------- K2bc: partials -> score -> context ----------------
__global__ void __launch_bounds__(256) k2bc_score_ctx(const float* __restrict__ enc,
                                                      const float* __restrict__ bf,
                                                      const float* __restrict__ mask,
                                                      float* __restrict__ out_score) {
    int b  = blockIdx.x;
    int et = blockIdx.y;
    int lo = g_lo[b], hi = g_hi[b];
    int tx = threadIdx.x & 31;
    int h  = threadIdx.x >> 5;
    int eg = et * 32 + tx;

    __shared__ float sc[256][8];
    float a0 = 0.f, a1 = 0.f, a2 = 0.f, a3 = 0.f;

    for (int st = lo; st <= hi; st += 256) {
        int tlen = hi - st + 1; if (tlen > 256) tlen = 256;
        __syncthreads();
        for (int idx = threadIdx.x; idx < tlen * 8; idx += 256) {
            int sr = idx >> 3, hh = idx & 7;
            int s = st + sr;
            const float* p = g_pf[b][s];
            float f = bf[hh];
            #pragma unroll
            for (int pp = 0; pp < 16; pp++) f += p[pp * 8 + hh];
            float alpha = softplusf(f) * mask[b * SEQ + s];
            float d = g_kap[b][hh] - (float)s;
            float scv = alpha * expf(-g_beta[b][hh] * d * d);
            sc[sr][hh] = scv;
            if (et == 0)
                out_score[((size_t)b * SEQ + s) * HEADS + hh] = scv;
        }
        __syncthreads();
        const float* ep = enc + ((size_t)b * SEQ + st) * ENC + eg;
        int sr = 0;
        for (; sr + 4 <= tlen; sr += 4) {
            a0 += sc[sr + 0][h] * ep[(size_t)(sr + 0) * ENC];
            a1 += sc[sr + 1][h] * ep[(size_t)(sr + 1) * ENC];
            a2 += sc[sr + 2][h] * ep[(size_t)(sr + 2) * ENC];
            a3 += sc[sr + 3][h] * ep[(size_t)(sr + 3) * ENC];
        }
        for (; sr < tlen; sr++)
            a0 += sc[sr][h] * ep[(size_t)sr * ENC];
    }
    g_ctx[b][h * ENC + eg] = (a0 + a1) + (a2 + a3);
}

// ---------------- K4: context @ Wfc + bfc ----------------
__global__ void __launch_bounds__(256) k4_final(const float* __restrict__ Wfc,
                                                const float* __restrict__ bfc,
                                                float* __restrict__ out_ctx) {
    int et = blockIdx.x, bg = blockIdx.y;
    int tx = threadIdx.x & 31;
    int js = threadIdx.x >> 5;
    int e  = et * 32 + tx;
    int j0 = js * 512;
    float a0 = 0.f, a1 = 0.f, a2 = 0.f, a3 = 0.f;
    const float* c0 = g_ctx[bg * 4 + 0];
    const float* c1 = g_ctx[bg * 4 + 1];
    const float* c2 = g_ctx[bg * 4 + 2];
    const float* c3 = g_ctx[bg * 4 + 3];
    #pragma unroll 8
    for (int j = j0; j < j0 + 512; j++) {
        float w = Wfc[(size_t)j * ENC + e];
        a0 += c0[j] * w;
        a1 += c1[j] * w;
        a2 += c2[j] * w;
        a3 += c3[j] * w;
    }
    __shared__ float red[8][4][32];
    red[js][0][tx] = a0; red[js][1][tx] = a1;
    red[js][2][tx] = a2; red[js][3][tx] = a3;
    __syncthreads();
    if (js < 4) {
        int bb = js;
        float s = 0.f;
        #pragma unroll
        for (int jj = 0; jj < 8; jj++) s += red[jj][bb][tx];
        out_ctx[(bg * 4 + bb) * ENC + e] = s + bfc[e];
    }
}

// ---------------- launch ----------------
extern "C" void kernel_launch(void* const* d_in, const int* in_sizes, int n_in,
                              void* d_out, int out_size) {
    const float* enc   = (const float*)d_in[0];
    const float* dec   = (const float*)d_in[1];
    const float* kappa = (const float*)d_in[2];
    const float* mask  = (const float*)d_in[3];
    const float* Wv    = (const float*)d_in[4];
    const float* bv    = (const float*)d_in[5];
    const float* Wq    = (const float*)d_in[6];
    const float* bq    = (const float*)d_in[7];
    const float* Wf    = (const float*)d_in[8];
    const float* bf    = (const float*)d_in[9];
    const float* Wb    = (const float*)d_in[10];
    const float* bb    = (const float*)d_in[11];
    const float* Wk    = (const float*)d_in[12];
    const float* bk    = (const float*)d_in[13];
    const float* Wfc   = (const float*)d_in[14];
    const float* bfc   = (const float*)d_in[15];

    float* out_ctx   = (float*)d_out;
    float* out_kappa = out_ctx + BS * ENC;
    float* out_score = out_kappa + BS * HEADS;

    cudaFuncSetAttribute(k2a_mma, cudaFuncAttributeMaxDynamicSharedMemorySize, SMEM_DYN);

    k0_heads<<<BS, 512>>>(dec, kappa, Wb, bb, Wk, bk, out_kappa);
    k0b_compact<<<1, 256>>>();
    kE_split<<<MAXTILES, 256>>>(enc);
    kW_split<<<dim3(ENC / 32, IH / 32), 256>>>(Wv);
    k1_query<<<dim3(16, 8), 256>>>(dec, Wq, bq, bv);
    k2a_mma<<<512, 256, SMEM_DYN>>>(Wf);
    cudaMemsetAsync(out_score, 0, (size_t)BS * SEQ * HEADS * sizeof(float), 0);
    k2bc_score_ctx<<<dim3(BS, 16), 256>>>(enc, bf, mask, out_score);
    k4_final<<<dim3(16, 8), 256>>>(Wfc, bfc, out_ctx);
}

// round 9
// speedup vs baseline: 3.1722x; 1.0829x over previous
#include <cuda_runtime.h>
#include <cuda_bf16.h>
#include <math.h>
#include <stdint.h>

#define BS    32
#define SEQ   2048
#define ENC   512
#define HEADS 8
#define IH    1024
#define DECIN 1024
#define SENT  0xFFFFFFFFu

#define MT 128
#define NT 64
#define NJT (IH / NT)
#define KC 64
#define MAXTILES 512

// ---------------- scratch ----------------
__device__ float         g_qv[BS][IH];
__device__ float         g_beta[BS][HEADS];
__device__ float         g_kap[BS][HEADS];
__device__ int           g_lo[BS];
__device__ int           g_hi[BS];
__device__ unsigned      g_rows[BS * SEQ + MT];
__device__ int           g_nt128;
__device__ float         g_pf[BS][SEQ][NJT * HEADS];
__device__ float         g_ctx[BS][HEADS * ENC];
__device__ __nv_bfloat16 g_WvThi[IH * ENC];
__device__ __nv_bfloat16 g_WvTlo[IH * ENC];
__device__ __nv_bfloat16 g_Ahi[(size_t)MAXTILES * MT * ENC];
__device__ __nv_bfloat16 g_Alo[(size_t)MAXTILES * MT * ENC];

__device__ __forceinline__ float softplusf(float x) {
    return fmaxf(x, 0.f) + log1pf(expf(-fabsf(x)));
}

#define SW128(x) ((x) ^ (((x) >> 3) & 0x70))

__device__ __forceinline__ uint32_t smem_u32(const void* p) {
    uint32_t a;
    asm("{ .reg .u64 t; cvta.to.shared.u64 t, %1; cvt.u32.u64 %0, t; }" : "=r"(a) : "l"(p));
    return a;
}
__device__ __forceinline__ void ldsm4(uint32_t* r, uint32_t addr) {
    asm volatile("ldmatrix.sync.aligned.m8n8.x4.shared.b16 {%0,%1,%2,%3}, [%4];"
                 : "=r"(r[0]), "=r"(r[1]), "=r"(r[2]), "=r"(r[3]) : "r"(addr));
}
__device__ __forceinline__ void mma16816(float* c, const uint32_t* a,
                                         uint32_t b0, uint32_t b1) {
    asm volatile("mma.sync.aligned.m16n8k16.row.col.f32.bf16.bf16.f32 "
                 "{%0,%1,%2,%3}, {%4,%5,%6,%7}, {%8,%9}, {%0,%1,%2,%3};"
                 : "+f"(c[0]), "+f"(c[1]), "+f"(c[2]), "+f"(c[3])
                 : "r"(a[0]), "r"(a[1]), "r"(a[2]), "r"(a[3]), "r"(b0), "r"(b1));
}

// ---------------- k_prep: merged kW_split (0..511) + k1_query (512..639) + k0_heads (640..671)
__global__ void __launch_bounds__(256) k_prep(const float* __restrict__ Wv,
                                              const float* __restrict__ dec,
                                              const float* __restrict__ Wq,
                                              const float* __restrict__ bq,
                                              const float* __restrict__ bv,
                                              const float* __restrict__ kappa_in,
                                              const float* __restrict__ Wb,
                                              const float* __restrict__ bb,
                                              const float* __restrict__ Wk,
                                              const float* __restrict__ bk,
                                              float* __restrict__ out_kappa) {
    __shared__ float smem[4 * DECIN + 4 * 4 * 64];   // k1 needs the most
    int bid = blockIdx.x;

    if (bid < 512) {
        // ===== kW_split: Wv -> bf16 hi/lo transposed [j][k] =====
        float (*s)[33] = (float (*)[33])smem;
        int k0 = (bid & 15) * 32, j0 = (bid >> 4) * 32;
        int jl = threadIdx.x & 31, kq = threadIdx.x >> 5;
        #pragma unroll
        for (int i = 0; i < 4; i++)
            s[kq * 4 + i][jl] = Wv[(size_t)(k0 + kq * 4 + i) * IH + j0 + jl];
        __syncthreads();
        int jr = threadIdx.x >> 3;
        int kg = (threadIdx.x & 7) * 4;
        __nv_bfloat16 hi[4], lo[4];
        #pragma unroll
        for (int i = 0; i < 4; i++) {
            float x = s[kg + i][jr];
            hi[i] = __float2bfloat16(x);
            lo[i] = __float2bfloat16(x - __bfloat162float(hi[i]));
        }
        size_t dst = (size_t)(j0 + jr) * ENC + k0 + kg;
        *(uint2*)(g_WvThi + dst) = *(const uint2*)hi;
        *(uint2*)(g_WvTlo + dst) = *(const uint2*)lo;
    } else if (bid < 640) {
        // ===== k1_query: qv = dec@Wq + bq + bv =====
        int id = bid - 512;
        int jt = id & 15, bg = id >> 4;
        int c  = threadIdx.x & 63;
        int ks = threadIdx.x >> 6;
        int j  = jt * 64 + c;
        float (*sdec)[DECIN] = (float (*)[DECIN])smem;
        float (*pacc)[4][64] = (float (*)[4][64])(smem + 4 * DECIN);
        for (int i = threadIdx.x; i < 4 * DECIN; i += 256) {
            int bb2 = i >> 10, k = i & (DECIN - 1);
            sdec[bb2][k] = dec[(bg * 4 + bb2) * DECIN + k];
        }
        __syncthreads();
        float a0 = 0.f, a1 = 0.f, a2 = 0.f, a3 = 0.f;
        int k0 = ks * 256;
        #pragma unroll 4
        for (int k = k0; k < k0 + 256; k++) {
            float w = Wq[k * IH + j];
            a0 += sdec[0][k] * w; a1 += sdec[1][k] * w;
            a2 += sdec[2][k] * w; a3 += sdec[3][k] * w;
        }
        pacc[ks][0][c] = a0; pacc[ks][1][c] = a1;
        pacc[ks][2][c] = a2; pacc[ks][3][c] = a3;
        __syncthreads();
        if (ks == 0) {
            float add = bq[j] + bv[j];
            #pragma unroll
            for (int bb2 = 0; bb2 < 4; bb2++) {
                float s2 = pacc[0][bb2][c] + pacc[1][bb2][c] + pacc[2][bb2][c] + pacc[3][bb2][c];
                g_qv[bg * 4 + bb2][j] = s2 + add;
            }
        }
    } else {
        // ===== k0_heads: beta/kappa + window =====
        int b = bid - 640;
        float* sdec = smem;
        float* sbeta = smem + DECIN;
        float* skap  = smem + DECIN + HEADS;
        for (int i = threadIdx.x; i < DECIN; i += 256)
            sdec[i] = dec[b * DECIN + i];
        __syncthreads();
        int w = threadIdx.x >> 5, lane = threadIdx.x & 31;
        #pragma unroll
        for (int rep = 0; rep < 2; rep++) {
            int p = w + rep * 8;          // 0..15
            int h = p & 7;
            const float* W = (p < 8) ? Wb : Wk;
            float acc = 0.f;
            for (int k = lane; k < DECIN; k += 32) acc += sdec[k] * W[k * HEADS + h];
            #pragma unroll
            for (int off = 16; off >= 1; off >>= 1)
                acc += __shfl_xor_sync(0xffffffffu, acc, off);
            if (lane == 0) {
                if (p < 8) {
                    float bv2 = softplusf(acc + bb[h]);
                    sbeta[h] = bv2;
                    g_beta[b][h] = bv2;
                } else {
                    float kv = kappa_in[b * HEADS + h] + softplusf(acc + bk[h]);
                    skap[h] = kv;
                    g_kap[b][h] = kv;
                    out_kappa[b * HEADS + h] = kv;
                }
            }
        }
        __syncthreads();
        if (threadIdx.x == 0) {
            float lof = 1e30f, hif = -1e30f;
            for (int h = 0; h < HEADS; h++) {
                float R = sqrtf(110.f / sbeta[h]);
                lof = fminf(lof, skap[h] - R);
                hif = fmaxf(hif, skap[h] + R);
            }
            int lo, hi;
            if (hif < 0.f || lof > (float)(SEQ - 1)) { lo = 0; hi = -1; }
            else {
                lo = (int)floorf(lof); if (lo < 0) lo = 0;
                hi = (int)ceilf(hif);  if (hi > SEQ - 1) hi = SEQ - 1;
            }
            g_lo[b] = lo; g_hi[b] = hi;
        }
    }
}

// ---------------- K0b: compact active rows (pad to 128) ----------------
__global__ void k0b_compact() {
    __shared__ int soff[BS + 1];
    int t = threadIdx.x;
    if (t == 0) {
        int off = 0;
        for (int b = 0; b < BS; b++) {
            soff[b] = off;
            int w = g_hi[b] - g_lo[b] + 1;
            if (w < 0) w = 0;
            off += w;
        }
        soff[BS] = off;
        int nt = (off + MT - 1) / MT;
        if (nt < 1) nt = 1;
        g_nt128 = nt;
    }
    __syncthreads();
    int total = soff[BS];
    int padded = ((total + MT - 1) / MT) * MT;
    if (padded < MT) padded = MT;
    for (int b = 0; b < BS; b++) {
        int lo = g_lo[b];
        int w  = soff[b + 1] - soff[b];
        int base = soff[b];
        for (int i = t; i < w; i += blockDim.x)
            g_rows[base + i] = ((unsigned)b << 16) | (unsigned)(lo + i);
    }
    for (int i = total + t; i < padded; i += blockDim.x)
        g_rows[i] = SENT;
}

// ---------------- kE: split compacted enc rows into bf16 hi/lo ----------------
__global__ void kE_split(const float* __restrict__ enc) {
    int tile = blockIdx.x;
    if (tile >= g_nt128) return;
    int row  = threadIdx.x >> 1;
    int half = threadIdx.x & 1;
    int grow = tile * MT + row;
    unsigned m = g_rows[grow];
    size_t dbase = (size_t)grow * ENC + half * 256;
    if (m == SENT) {
        uint4 z = make_uint4(0, 0, 0, 0);
        #pragma unroll 8
        for (int q = 0; q < 32; q++) {
            ((uint4*)(g_Ahi + dbase))[q] = z;
            ((uint4*)(g_Alo + dbase))[q] = z;
        }
        return;
    }
    const float4* src = (const float4*)(enc + ((size_t)(m >> 16) * SEQ + (m & 0xFFFF)) * ENC
                                        + half * 256);
    #pragma unroll 4
    for (int q = 0; q < 32; q++) {
        float4 v0 = src[q * 2], v1 = src[q * 2 + 1];
        float x[8] = {v0.x, v0.y, v0.z, v0.w, v1.x, v1.y, v1.z, v1.w};
        __nv_bfloat16 hi[8], lo[8];
        #pragma unroll
        for (int i = 0; i < 8; i++) {
            hi[i] = __float2bfloat16(x[i]);
            lo[i] = __float2bfloat16(x[i] - __bfloat162float(hi[i]));
        }
        ((uint4*)(g_Ahi + dbase))[q] = *(const uint4*)hi;
        ((uint4*)(g_Alo + dbase))[q] = *(const uint4*)lo;
    }
}

// ---------------- K2a: warp-MMA bf16-split value GEMM + tanh + partial @Wf ----------------
#define OFF_A_HI 0
#define OFF_A_LO 16384
#define OFF_B_HI 32768
#define OFF_B_LO 40960
#define OFF_WF   49152
#define OFF_META 51200
#define SMEM_DYN (51712 + 1024)

__global__ void __launch_bounds__(256) k2a_mma(const float* __restrict__ Wf) {
    int nt = g_nt128;
    int total_tiles = nt * NJT;

    extern __shared__ char dsm[];
    uint32_t b0 = smem_u32(dsm);
    uint32_t ab = (b0 + 1023u) & ~1023u;
    char* dyn = dsm + (ab - b0);
    float*    sWf   = (float*)(dyn + OFF_WF);
    unsigned* smeta = (unsigned*)(dyn + OFF_META);

    int tid  = threadIdx.x;
    int wid  = tid >> 5, lane = tid & 31;

    int wm = wid * 16;
    uint32_t a_rb   = (uint32_t)((wm + (lane & 15)) * 128 + ((lane & 16) ? 16 : 0));
    uint32_t a_msk  = (a_rb >> 3) & 0x70;
    uint32_t b_rb[4], b_msk[4];
    #pragma unroll
    for (int p = 0; p < 4; p++) {
        int n = p * 16 + (lane & 7) + ((lane & 16) ? 8 : 0);
        b_rb[p]  = (uint32_t)(n * 128 + ((lane & 8) ? 16 : 0));
        b_msk[p] = (b_rb[p] >> 3) & 0x70;
    }
    uint32_t Ahi_b = ab + OFF_A_HI, Alo_b = ab + OFF_A_LO;
    uint32_t Bhi_b = ab + OFF_B_HI, Blo_b = ab + OFF_B_LO;

    int srow = tid >> 1, shalf = tid & 1;
    int bn   = tid >> 2, bq = (tid & 3) * 2;

    for (int t = blockIdx.x; t < total_tiles; t += gridDim.x) {
        int mtile = t >> 4;
        int jt    = t & 15;
        int jbase = jt * NT;

        __syncthreads();
        if (tid < MT) smeta[tid] = g_rows[mtile * MT + tid];
        for (int i = tid; i < NT * 8; i += 256) sWf[i] = Wf[jbase * 8 + i];

        float acc[8][4];
        #pragma unroll
        for (int nf = 0; nf < 8; nf++)
            #pragma unroll
            for (int q = 0; q < 4; q++) acc[nf][q] = 0.f;

        const uint4* Ah_src = (const uint4*)(g_Ahi + ((size_t)(mtile * MT + srow)) * ENC);
        const uint4* Al_src = (const uint4*)(g_Alo + ((size_t)(mtile * MT + srow)) * ENC);
        const uint4* Bh_src = (const uint4*)(g_WvThi + (size_t)(jbase + bn) * ENC);
        const uint4* Bl_src = (const uint4*)(g_WvTlo + (size_t)(jbase + bn) * ENC);

        for (int kc = 0; kc < ENC / KC; kc++) {
            int kk8 = kc * (KC / 8);
            __syncthreads();
            #pragma unroll
            for (int q = 0; q < 4; q++) {
                uint32_t o = SW128((uint32_t)(srow * 128 + shalf * 64 + q * 16));
                *(uint4*)(dyn + OFF_A_HI + o) = Ah_src[kk8 + shalf * 4 + q];
                *(uint4*)(dyn + OFF_A_LO + o) = Al_src[kk8 + shalf * 4 + q];
            }
            #pragma unroll
            for (int q = 0; q < 2; q++) {
                uint32_t o = SW128((uint32_t)(bn * 128 + (bq + q) * 16));
                *(uint4*)(dyn + OFF_B_HI + o) = Bh_src[kk8 + bq + q];
                *(uint4*)(dyn + OFF_B_LO + o) = Bl_src[kk8 + bq + q];
            }
            __syncthreads();
            #pragma unroll
            for (int ks = 0; ks < 4; ks++) {
                uint32_t ah[4], al[4];
                ldsm4(ah, Ahi_b + ((a_rb + ks * 32) ^ a_msk));
                ldsm4(al, Alo_b + ((a_rb + ks * 32) ^ a_msk));
                #pragma unroll
                for (int p = 0; p < 4; p++) {
                    uint32_t bh[4], bl[4];
                    ldsm4(bh, Bhi_b + ((b_rb[p] + ks * 32) ^ b_msk[p]));
                    ldsm4(bl, Blo_b + ((b_rb[p] + ks * 32) ^ b_msk[p]));
                    mma16816(acc[p * 2],     ah, bh[0], bh[1]);
                    mma16816(acc[p * 2],     ah, bl[0], bl[1]);
                    mma16816(acc[p * 2],     al, bh[0], bh[1]);
                    mma16816(acc[p * 2 + 1], ah, bh[2], bh[3]);
                    mma16816(acc[p * 2 + 1], ah, bl[2], bl[3]);
                    mma16816(acc[p * 2 + 1], al, bh[2], bh[3]);
                }
            }
        }

        int r0 = wm + (lane >> 2);
        int r1 = r0 + 8;
        unsigned m0 = smeta[r0], m1 = smeta[r1];
        const float* qv0 = &g_qv[(m0 != SENT) ? (m0 >> 16) : 0][jbase];
        const float* qv1 = &g_qv[(m1 != SENT) ? (m1 >> 16) : 0][jbase];
        float pf0[8], pf1[8];
        #pragma unroll
        for (int h = 0; h < 8; h++) { pf0[h] = 0.f; pf1[h] = 0.f; }
        #pragma unroll
        for (int nf = 0; nf < 8; nf++) {
            int jl = nf * 8 + 2 * (lane & 3);
            float hv00 = (m0 != SENT) ? tanhf(qv0[jl]     + acc[nf][0]) : 0.f;
            float hv01 = (m0 != SENT) ? tanhf(qv0[jl + 1] + acc[nf][1]) : 0.f;
            float hv10 = (m1 != SENT) ? tanhf(qv1[jl]     + acc[nf][2]) : 0.f;
            float hv11 = (m1 != SENT) ? tanhf(qv1[jl + 1] + acc[nf][3]) : 0.f;
            const float* w0 = &sWf[jl * 8];
            const float* w1 = &sWf[(jl + 1) * 8];
            #pragma unroll
            for (int h = 0; h < 8; h++) {
                pf0[h] += hv00 * w0[h] + hv01 * w1[h];
                pf1[h] += hv10 * w0[h] + hv11 * w1[h];
            }
        }
        #pragma unroll
        for (int h = 0; h < 8; h++) {
            pf0[h] += __shfl_xor_sync(0xffffffffu, pf0[h], 1);
            pf0[h] += __shfl_xor_sync(0xffffffffu, pf0[h], 2);
            pf1[h] += __shfl_xor_sync(0xffffffffu, pf1[h], 1);
            pf1[h] += __shfl_xor_sync(0xffffffffu, pf1[h], 2);
        }
        if ((lane & 3) == 0) {
            if (m0 != SENT) {
                float* dst = &g_pf[m0 >> 16][m0 & 0xFFFF][jt * 8];
                *(float4*)dst       = make_float4(pf0[0], pf0[1], pf0[2], pf0[3]);
                *(float4*)(dst + 4) = make_float4(pf0[4], pf0[5], pf0[6], pf0[7]);
            }
            if (m1 != SENT) {
                float* dst = &g_pf[m1 >> 16][m1 & 0xFFFF][jt * 8];
                *(float4*)dst       = make_float4(pf1[0], pf1[1], pf1[2], pf1[3]);
                *(float4*)(dst + 4) = make_float4(pf1[4], pf1[5], pf1[6], pf1[7]);
            }
        }
    }
}

// ---------------- K2bc: partials -> score -> context ----------------
__global__ void __launch_bounds__(256) k2bc_score_ctx(const float* __restrict__ enc,
                                                      const float* __restrict__ bf,
                                                      const float* __restrict__ mask,
                                                      float* __restrict__ out_score) {
    int b  = blockIdx.x;
    int et = blockIdx.y;
    int lo = g_lo[b], hi = g_hi[b];
    int tx = threadIdx.x & 31;
    int h  = threadIdx.x >> 5;
    int eg = et * 32 + tx;

    __shared__ float sc[256][8];
    float a0 = 0.f, a1 = 0.f, a2 = 0.f, a3 = 0.f;

    for (int st = lo; st <= hi; st += 256) {
        int tlen = hi - st + 1; if (tlen > 256) tlen = 256;
        __syncthreads();
        for (int idx = threadIdx.x; idx < tlen * 8; idx += 256) {
            int sr = idx >> 3, hh = idx & 7;
            int s = st + sr;
            const float* p = g_pf[b][s];
            float f = bf[hh];
            #pragma unroll
            for (int pp = 0; pp < 16; pp++) f += p[pp * 8 + hh];
            float alpha = softplusf(f) * mask[b * SEQ + s];
            float d = g_kap[b][hh] - (float)s;
            float scv = alpha * expf(-g_beta[b][hh] * d * d);
            sc[sr][hh] = scv;
            if (et == 0)
                out_score[((size_t)b * SEQ + s) * HEADS + hh] = scv;
        }
        __syncthreads();
        const float* ep = enc + ((size_t)b * SEQ + st) * ENC + eg;
        int sr = 0;
        for (; sr + 4 <= tlen; sr += 4) {
            a0 += sc[sr + 0][h] * ep[(size_t)(sr + 0) * ENC];
            a1 += sc[sr + 1][h] * ep[(size_t)(sr + 1) * ENC];
            a2 += sc[sr + 2][h] * ep[(size_t)(sr + 2) * ENC];
            a3 += sc[sr + 3][h] * ep[(size_t)(sr + 3) * ENC];
        }
        for (; sr < tlen; sr++)
            a0 += sc[sr][h] * ep[(size_t)sr * ENC];
    }
    g_ctx[b][h * ENC + eg] = (a0 + a1) + (a2 + a3);
}

// ---------------- K4: context @ Wfc + bfc ----------------
__global__ void __launch_bounds__(256) k4_final(const float* __restrict__ Wfc,
                                                const float* __restrict__ bfc,
                                                float* __restrict__ out_ctx) {
    int et = blockIdx.x, bg = blockIdx.y;
    int tx = threadIdx.x & 31;
    int js = threadIdx.x >> 5;
    int e  = et * 32 + tx;
    int j0 = js * 512;
    float a0 = 0.f, a1 = 0.f, a2 = 0.f, a3 = 0.f;
    const float* c0 = g_ctx[bg * 4 + 0];
    const float* c1 = g_ctx[bg * 4 + 1];
    const float* c2 = g_ctx[bg * 4 + 2];
    const float* c3 = g_ctx[bg * 4 + 3];
    #pragma unroll 8
    for (int j = j0; j < j0 + 512; j++) {
        float w = Wfc[(size_t)j * ENC + e];
        a0 += c0[j] * w;
        a1 += c1[j] * w;
        a2 += c2[j] * w;
        a3 += c3[j] * w;
    }
    __shared__ float red[8][4][32];
    red[js][0][tx] = a0; red[js][1][tx] = a1;
    red[js][2][tx] = a2; red[js][3][tx] = a3;
    __syncthreads();
    if (js < 4) {
        int bb = js;
        float s = 0.f;
        #pragma unroll
        for (int jj = 0; jj < 8; jj++) s += red[jj][bb][tx];
        out_ctx[(bg * 4 + bb) * ENC + e] = s + bfc[e];
    }
}

// ---------------- launch ----------------
extern "C" void kernel_launch(void* const* d_in, const int* in_sizes, int n_in,
                              void* d_out, int out_size) {
    const float* enc   = (const float*)d_in[0];
    const float* dec   = (const float*)d_in[1];
    const float* kappa = (const float*)d_in[2];
    const float* mask  = (const float*)d_in[3];
    const float* Wv    = (const float*)d_in[4];
    const float* bv    = (const float*)d_in[5];
    const float* Wq    = (const float*)d_in[6];
    const float* bq    = (const float*)d_in[7];
    const float* Wf    = (const float*)d_in[8];
    const float* bf    = (const float*)d_in[9];
    const float* Wb    = (const float*)d_in[10];
    const float* bb    = (const float*)d_in[11];
    const float* Wk    = (const float*)d_in[12];
    const float* bk    = (const float*)d_in[13];
    const float* Wfc   = (const float*)d_in[14];
    const float* bfc   = (const float*)d_in[15];

    float* out_ctx   = (float*)d_out;
    float* out_kappa = out_ctx + BS * ENC;
    float* out_score = out_kappa + BS * HEADS;

    cudaFuncSetAttribute(k2a_mma, cudaFuncAttributeMaxDynamicSharedMemorySize, SMEM_DYN);

    cudaMemsetAsync(out_score, 0, (size_t)BS * SEQ * HEADS * sizeof(float), 0);
    k_prep<<<672, 256>>>(Wv, dec, Wq, bq, bv, kappa, Wb, bb, Wk, bk, out_kappa);
    k0b_compact<<<1, 256>>>();
    kE_split<<<MAXTILES, 256>>>(enc);
    k2a_mma<<<512, 256, SMEM_DYN>>>(Wf);
    k2bc_score_ctx<<<dim3(BS, 16), 256>>>(enc, bf, mask, out_score);
    k4_final<<<dim3(16, 8), 256>>>(Wfc, bfc, out_ctx);
}

// round 10
// speedup vs baseline: 3.3574x; 1.0584x over previous
#include <cuda_runtime.h>
#include <cuda_bf16.h>
#include <math.h>
#include <stdint.h>

#define BS    32
#define SEQ   2048
#define ENC   512
#define HEADS 8
#define IH    1024
#define DECIN 1024
#define SENT  0xFFFFFFFFu

#define MT 64            // rows per m-tile (k2a)
#define NT 64            // j per n-tile
#define NJT (IH / NT)    // 16
#define KC 64
#define MAXTILES 512     // kE 128-row tiles

// ---------------- scratch ----------------
__device__ float         g_qv[BS][IH];
__device__ float         g_beta[BS][HEADS];
__device__ float         g_kap[BS][HEADS];
__device__ int           g_lo[BS];
__device__ int           g_hi[BS];
__device__ unsigned      g_rows[BS * SEQ + 128];
__device__ int           g_nt128;    // 128-row tiles (kE)
__device__ int           g_nt64;     // 64-row tiles (k2a)
__device__ float         g_pf[BS][SEQ][NJT * HEADS];
__device__ float         g_ctx[BS][HEADS * ENC];
__device__ __nv_bfloat16 g_WvThi[IH * ENC];
__device__ __nv_bfloat16 g_WvTlo[IH * ENC];
__device__ __nv_bfloat16 g_Ahi[(size_t)MAXTILES * 128 * ENC];
__device__ __nv_bfloat16 g_Alo[(size_t)MAXTILES * 128 * ENC];

__device__ __forceinline__ float softplusf(float x) {
    return fmaxf(x, 0.f) + log1pf(expf(-fabsf(x)));
}

#define SW128(x) ((x) ^ (((x) >> 3) & 0x70))

__device__ __forceinline__ uint32_t smem_u32(const void* p) {
    uint32_t a;
    asm("{ .reg .u64 t; cvta.to.shared.u64 t, %1; cvt.u32.u64 %0, t; }" : "=r"(a) : "l"(p));
    return a;
}
__device__ __forceinline__ void ldsm4(uint32_t* r, uint32_t addr) {
    asm volatile("ldmatrix.sync.aligned.m8n8.x4.shared.b16 {%0,%1,%2,%3}, [%4];"
                 : "=r"(r[0]), "=r"(r[1]), "=r"(r[2]), "=r"(r[3]) : "r"(addr));
}
__device__ __forceinline__ void mma16816(float* c, const uint32_t* a,
                                         uint32_t b0, uint32_t b1) {
    asm volatile("mma.sync.aligned.m16n8k16.row.col.f32.bf16.bf16.f32 "
                 "{%0,%1,%2,%3}, {%4,%5,%6,%7}, {%8,%9}, {%0,%1,%2,%3};"
                 : "+f"(c[0]), "+f"(c[1]), "+f"(c[2]), "+f"(c[3])
                 : "r"(a[0]), "r"(a[1]), "r"(a[2]), "r"(a[3]), "r"(b0), "r"(b1));
}
__device__ __forceinline__ void cp16(uint32_t dst, const void* src) {
    asm volatile("cp.async.cg.shared.global [%0], [%1], 16;" :: "r"(dst), "l"(src));
}
#define CP_COMMIT() asm volatile("cp.async.commit_group;" ::: "memory")
#define CP_WAIT(n)  asm volatile("cp.async.wait_group %0;" :: "n"(n) : "memory")

// ---------------- k_prep: merged kW_split (0..511) + k1_query (512..639) + k0_heads (640..671)
__global__ void __launch_bounds__(256) k_prep(const float* __restrict__ Wv,
                                              const float* __restrict__ dec,
                                              const float* __restrict__ Wq,
                                              const float* __restrict__ bq,
                                              const float* __restrict__ bv,
                                              const float* __restrict__ kappa_in,
                                              const float* __restrict__ Wb,
                                              const float* __restrict__ bb,
                                              const float* __restrict__ Wk,
                                              const float* __restrict__ bk,
                                              float* __restrict__ out_kappa) {
    __shared__ float smem[4 * DECIN + 4 * 4 * 64];
    int bid = blockIdx.x;

    if (bid < 512) {
        float (*s)[33] = (float (*)[33])smem;
        int k0 = (bid & 15) * 32, j0 = (bid >> 4) * 32;
        int jl = threadIdx.x & 31, kq = threadIdx.x >> 5;
        #pragma unroll
        for (int i = 0; i < 4; i++)
            s[kq * 4 + i][jl] = Wv[(size_t)(k0 + kq * 4 + i) * IH + j0 + jl];
        __syncthreads();
        int jr = threadIdx.x >> 3;
        int kg = (threadIdx.x & 7) * 4;
        __nv_bfloat16 hi[4], lo[4];
        #pragma unroll
        for (int i = 0; i < 4; i++) {
            float x = s[kg + i][jr];
            hi[i] = __float2bfloat16(x);
            lo[i] = __float2bfloat16(x - __bfloat162float(hi[i]));
        }
        size_t dst = (size_t)(j0 + jr) * ENC + k0 + kg;
        *(uint2*)(g_WvThi + dst) = *(const uint2*)hi;
        *(uint2*)(g_WvTlo + dst) = *(const uint2*)lo;
    } else if (bid < 640) {
        int id = bid - 512;
        int jt = id & 15, bg = id >> 4;
        int c  = threadIdx.x & 63;
        int ks = threadIdx.x >> 6;
        int j  = jt * 64 + c;
        float (*sdec)[DECIN] = (float (*)[DECIN])smem;
        float (*pacc)[4][64] = (float (*)[4][64])(smem + 4 * DECIN);
        for (int i = threadIdx.x; i < 4 * DECIN; i += 256) {
            int bb2 = i >> 10, k = i & (DECIN - 1);
            sdec[bb2][k] = dec[(bg * 4 + bb2) * DECIN + k];
        }
        __syncthreads();
        float a0 = 0.f, a1 = 0.f, a2 = 0.f, a3 = 0.f;
        int k0 = ks * 256;
        #pragma unroll 4
        for (int k = k0; k < k0 + 256; k++) {
            float w = Wq[k * IH + j];
            a0 += sdec[0][k] * w; a1 += sdec[1][k] * w;
            a2 += sdec[2][k] * w; a3 += sdec[3][k] * w;
        }
        pacc[ks][0][c] = a0; pacc[ks][1][c] = a1;
        pacc[ks][2][c] = a2; pacc[ks][3][c] = a3;
        __syncthreads();
        if (ks == 0) {
            float add = bq[j] + bv[j];
            #pragma unroll
            for (int bb2 = 0; bb2 < 4; bb2++) {
                float s2 = pacc[0][bb2][c] + pacc[1][bb2][c] + pacc[2][bb2][c] + pacc[3][bb2][c];
                g_qv[bg * 4 + bb2][j] = s2 + add;
            }
        }
    } else {
        int b = bid - 640;
        float* sdec = smem;
        float* sbeta = smem + DECIN;
        float* skap  = smem + DECIN + HEADS;
        for (int i = threadIdx.x; i < DECIN; i += 256)
            sdec[i] = dec[b * DECIN + i];
        __syncthreads();
        int w = threadIdx.x >> 5, lane = threadIdx.x & 31;
        #pragma unroll
        for (int rep = 0; rep < 2; rep++) {
            int p = w + rep * 8;
            int h = p & 7;
            const float* W = (p < 8) ? Wb : Wk;
            float acc = 0.f;
            for (int k = lane; k < DECIN; k += 32) acc += sdec[k] * W[k * HEADS + h];
            #pragma unroll
            for (int off = 16; off >= 1; off >>= 1)
                acc += __shfl_xor_sync(0xffffffffu, acc, off);
            if (lane == 0) {
                if (p < 8) {
                    float bv2 = softplusf(acc + bb[h]);
                    sbeta[h] = bv2;
                    g_beta[b][h] = bv2;
                } else {
                    float kv = kappa_in[b * HEADS + h] + softplusf(acc + bk[h]);
                    skap[h] = kv;
                    g_kap[b][h] = kv;
                    out_kappa[b * HEADS + h] = kv;
                }
            }
        }
        __syncthreads();
        if (threadIdx.x == 0) {
            float lof = 1e30f, hif = -1e30f;
            for (int h = 0; h < HEADS; h++) {
                float R = sqrtf(110.f / sbeta[h]);
                lof = fminf(lof, skap[h] - R);
                hif = fmaxf(hif, skap[h] + R);
            }
            int lo, hi;
            if (hif < 0.f || lof > (float)(SEQ - 1)) { lo = 0; hi = -1; }
            else {
                lo = (int)floorf(lof); if (lo < 0) lo = 0;
                hi = (int)ceilf(hif);  if (hi > SEQ - 1) hi = SEQ - 1;
            }
            g_lo[b] = lo; g_hi[b] = hi;
        }
    }
}

// ---------------- K0b: compact active rows (pad to 128) ----------------
__global__ void k0b_compact() {
    __shared__ int soff[BS + 1];
    int t = threadIdx.x;
    if (t == 0) {
        int off = 0;
        for (int b = 0; b < BS; b++) {
            soff[b] = off;
            int w = g_hi[b] - g_lo[b] + 1;
            if (w < 0) w = 0;
            off += w;
        }
        soff[BS] = off;
        int nt = (off + 127) / 128;
        if (nt < 1) nt = 1;
        g_nt128 = nt;
        int n64 = (off + MT - 1) / MT;
        if (n64 < 1) n64 = 1;
        g_nt64 = n64;
    }
    __syncthreads();
    int total = soff[BS];
    int padded = ((total + 127) / 128) * 128;
    if (padded < 128) padded = 128;
    for (int b = 0; b < BS; b++) {
        int lo = g_lo[b];
        int w  = soff[b + 1] - soff[b];
        int base = soff[b];
        for (int i = t; i < w; i += blockDim.x)
            g_rows[base + i] = ((unsigned)b << 16) | (unsigned)(lo + i);
    }
    for (int i = total + t; i < padded; i += blockDim.x)
        g_rows[i] = SENT;
}

// ---------------- kE: split compacted enc rows into bf16 hi/lo ----------------
__global__ void kE_split(const float* __restrict__ enc) {
    int tile = blockIdx.x;
    if (tile >= g_nt128) return;
    int row  = threadIdx.x >> 1;
    int half = threadIdx.x & 1;
    int grow = tile * 128 + row;
    unsigned m = g_rows[grow];
    size_t dbase = (size_t)grow * ENC + half * 256;
    if (m == SENT) {
        uint4 z = make_uint4(0, 0, 0, 0);
        #pragma unroll 8
        for (int q = 0; q < 32; q++) {
            ((uint4*)(g_Ahi + dbase))[q] = z;
            ((uint4*)(g_Alo + dbase))[q] = z;
        }
        return;
    }
    const float4* src = (const float4*)(enc + ((size_t)(m >> 16) * SEQ + (m & 0xFFFF)) * ENC
                                        + half * 256);
    #pragma unroll 4
    for (int q = 0; q < 32; q++) {
        float4 v0 = src[q * 2], v1 = src[q * 2 + 1];
        float x[8] = {v0.x, v0.y, v0.z, v0.w, v1.x, v1.y, v1.z, v1.w};
        __nv_bfloat16 hi[8], lo[8];
        #pragma unroll
        for (int i = 0; i < 8; i++) {
            hi[i] = __float2bfloat16(x[i]);
            lo[i] = __float2bfloat16(x[i] - __bfloat162float(hi[i]));
        }
        ((uint4*)(g_Ahi + dbase))[q] = *(const uint4*)hi;
        ((uint4*)(g_Alo + dbase))[q] = *(const uint4*)lo;
    }
}

// ---------------- K2a: pipelined warp-MMA bf16-split GEMM + tanh + partial @Wf ----------------
// 128 threads (4 warps), tile 64 rows x 64 j, K chunks of 64, 2-stage cp.async pipeline.
#define ST_STRIDE 32768
#define OFF_AH 0
#define OFF_AL 8192
#define OFF_BH 16384
#define OFF_BL 24576
#define OFF_WF   (2 * ST_STRIDE)
#define OFF_META (OFF_WF + 2048)
#define SMEM_DYN (OFF_META + 256 + 1024)

__global__ void __launch_bounds__(128) k2a_mma(const float* __restrict__ Wf) {
    int total_tiles = g_nt64 * NJT;

    extern __shared__ char dsm[];
    uint32_t b0 = smem_u32(dsm);
    uint32_t ab = (b0 + 1023u) & ~1023u;
    char* dyn = dsm + (ab - b0);
    float*    sWf   = (float*)(dyn + OFF_WF);
    unsigned* smeta = (unsigned*)(dyn + OFF_META);

    int tid  = threadIdx.x;
    int wid  = tid >> 5, lane = tid & 31;

    int wm = wid * 16;
    uint32_t a_rb  = (uint32_t)((wm + (lane & 15)) * 128 + ((lane & 16) ? 16 : 0));
    uint32_t a_msk = (a_rb >> 3) & 0x70;
    uint32_t b_rb[4], b_msk[4];
    #pragma unroll
    for (int p = 0; p < 4; p++) {
        int n = p * 16 + (lane & 7) + ((lane & 16) ? 8 : 0);
        b_rb[p]  = (uint32_t)(n * 128 + ((lane & 8) ? 16 : 0));
        b_msk[p] = (b_rb[p] >> 3) & 0x70;
    }

    int srow = tid >> 1, shalf = tid & 1;   // 64 rows x 2 halves

    for (int t = blockIdx.x; t < total_tiles; t += gridDim.x) {
        int mtile = t >> 4;
        int jt    = t & 15;
        int jbase = jt * NT;

        __syncthreads();   // prior tile fully consumed (smem + buffers)
        if (tid < MT) smeta[tid] = g_rows[mtile * MT + tid];
        #pragma unroll
        for (int i = 0; i < 4; i++) sWf[tid + i * 128] = Wf[jbase * 8 + tid + i * 128];

        const char* Ah_base = (const char*)(g_Ahi + (size_t)(mtile * MT + srow) * ENC) + shalf * 64;
        const char* Al_base = (const char*)(g_Alo + (size_t)(mtile * MT + srow) * ENC) + shalf * 64;
        const char* Bh_base = (const char*)(g_WvThi + (size_t)(jbase + srow) * ENC) + shalf * 64;
        const char* Bl_base = (const char*)(g_WvTlo + (size_t)(jbase + srow) * ENC) + shalf * 64;

        #define STAGE(kc_, buf_) do { \
            uint32_t sb_ = ab + (buf_) * ST_STRIDE; \
            _Pragma("unroll") \
            for (int q = 0; q < 4; q++) { \
                uint32_t o_ = SW128((uint32_t)(srow * 128 + shalf * 64 + q * 16)); \
                cp16(sb_ + OFF_AH + o_, Ah_base + (kc_) * 128 + q * 16); \
                cp16(sb_ + OFF_AL + o_, Al_base + (kc_) * 128 + q * 16); \
                cp16(sb_ + OFF_BH + o_, Bh_base + (kc_) * 128 + q * 16); \
                cp16(sb_ + OFF_BL + o_, Bl_base + (kc_) * 128 + q * 16); \
            } \
        } while (0)

        STAGE(0, 0);
        CP_COMMIT();

        float acc[8][4];
        #pragma unroll
        for (int nf = 0; nf < 8; nf++)
            #pragma unroll
            for (int q = 0; q < 4; q++) acc[nf][q] = 0.f;

        #pragma unroll
        for (int kc = 0; kc < ENC / KC; kc++) {
            __syncthreads();               // all warps done with buffer (kc+1)&1 from kc-1
            if (kc < ENC / KC - 1) {
                STAGE(kc + 1, (kc + 1) & 1);
                CP_COMMIT();
                CP_WAIT(1);
            } else {
                CP_WAIT(0);
            }
            __syncthreads();               // staged chunk kc visible to all

            uint32_t mb = ab + (kc & 1) * ST_STRIDE;
            #pragma unroll
            for (int ks = 0; ks < 4; ks++) {
                uint32_t ah[4], al[4];
                ldsm4(ah, mb + OFF_AH + ((a_rb + ks * 32) ^ a_msk));
                ldsm4(al, mb + OFF_AL + ((a_rb + ks * 32) ^ a_msk));
                uint32_t bh[4][4], bl[4][4];
                #pragma unroll
                for (int p = 0; p < 4; p++) {
                    ldsm4(bh[p], mb + OFF_BH + ((b_rb[p] + ks * 32) ^ b_msk[p]));
                    ldsm4(bl[p], mb + OFF_BL + ((b_rb[p] + ks * 32) ^ b_msk[p]));
                }
                #pragma unroll
                for (int p = 0; p < 4; p++) {
                    mma16816(acc[p * 2],     ah, bh[p][0], bh[p][1]);
                    mma16816(acc[p * 2 + 1], ah, bh[p][2], bh[p][3]);
                }
                #pragma unroll
                for (int p = 0; p < 4; p++) {
                    mma16816(acc[p * 2],     ah, bl[p][0], bl[p][1]);
                    mma16816(acc[p * 2 + 1], ah, bl[p][2], bl[p][3]);
                }
                #pragma unroll
                for (int p = 0; p < 4; p++) {
                    mma16816(acc[p * 2],     al, bh[p][0], bh[p][1]);
                    mma16816(acc[p * 2 + 1], al, bh[p][2], bh[p][3]);
                }
            }
        }
        #undef STAGE

        // ---- epilogue ----
        int r0 = wm + (lane >> 2);
        int r1 = r0 + 8;
        unsigned m0 = smeta[r0], m1 = smeta[r1];
        const float* qv0 = &g_qv[(m0 != SENT) ? (m0 >> 16) : 0][jbase];
        const float* qv1 = &g_qv[(m1 != SENT) ? (m1 >> 16) : 0][jbase];
        float pf0[8], pf1[8];
        #pragma unroll
        for (int h = 0; h < 8; h++) { pf0[h] = 0.f; pf1[h] = 0.f; }
        #pragma unroll
        for (int nf = 0; nf < 8; nf++) {
            int jl = nf * 8 + 2 * (lane & 3);
            float hv00 = (m0 != SENT) ? tanhf(qv0[jl]     + acc[nf][0]) : 0.f;
            float hv01 = (m0 != SENT) ? tanhf(qv0[jl + 1] + acc[nf][1]) : 0.f;
            float hv10 = (m1 != SENT) ? tanhf(qv1[jl]     + acc[nf][2]) : 0.f;
            float hv11 = (m1 != SENT) ? tanhf(qv1[jl + 1] + acc[nf][3]) : 0.f;
            const float* w0 = &sWf[jl * 8];
            const float* w1 = &sWf[(jl + 1) * 8];
            #pragma unroll
            for (int h = 0; h < 8; h++) {
                pf0[h] += hv00 * w0[h] + hv01 * w1[h];
                pf1[h] += hv10 * w0[h] + hv11 * w1[h];
            }
        }
        #pragma unroll
        for (int h = 0; h < 8; h++) {
            pf0[h] += __shfl_xor_sync(0xffffffffu, pf0[h], 1);
            pf0[h] += __shfl_xor_sync(0xffffffffu, pf0[h], 2);
            pf1[h] += __shfl_xor_sync(0xffffffffu, pf1[h], 1);
            pf1[h] += __shfl_xor_sync(0xffffffffu, pf1[h], 2);
        }
        if ((lane & 3) == 0) {
            if (m0 != SENT) {
                float* dst = &g_pf[m0 >> 16][m0 & 0xFFFF][jt * 8];
                *(float4*)dst       = make_float4(pf0[0], pf0[1], pf0[2], pf0[3]);
                *(float4*)(dst + 4) = make_float4(pf0[4], pf0[5], pf0[6], pf0[7]);
            }
            if (m1 != SENT) {
                float* dst = &g_pf[m1 >> 16][m1 & 0xFFFF][jt * 8];
                *(float4*)dst       = make_float4(pf1[0], pf1[1], pf1[2], pf1[3]);
                *(float4*)(dst + 4) = make_float4(pf1[4], pf1[5], pf1[6], pf1[7]);
            }
        }
    }
}

// ---------------- K2bc: partials -> score -> context ----------------
__global__ void __launch_bounds__(256) k2bc_score_ctx(const float* __restrict__ enc,
                                                      const float* __restrict__ bf,
                                                      const float* __restrict__ mask,
                                                      float* __restrict__ out_score) {
    int b  = blockIdx.x;
    int et = blockIdx.y;
    int lo = g_lo[b], hi = g_hi[b];
    int tx = threadIdx.x & 31;
    int h  = threadIdx.x >> 5;
    int eg = et * 32 + tx;

    __shared__ float sc[256][8];
    float a0 = 0.f, a1 = 0.f, a2 = 0.f, a3 = 0.f;

    for (int st = lo; st <= hi; st += 256) {
        int tlen = hi - st + 1; if (tlen > 256) tlen = 256;
        __syncthreads();
        for (int idx = threadIdx.x; idx < tlen * 8; idx += 256) {
            int sr = idx >> 3, hh = idx & 7;
            int s = st + sr;
            const float* p = g_pf[b][s];
            float f = bf[hh];
            #pragma unroll
            for (int pp = 0; pp < 16; pp++) f += p[pp * 8 + hh];
            float alpha = softplusf(f) * mask[b * SEQ + s];
            float d = g_kap[b][hh] - (float)s;
            float scv = alpha * expf(-g_beta[b][hh] * d * d);
            sc[sr][hh] = scv;
            if (et == 0)
                out_score[((size_t)b * SEQ + s) * HEADS + hh] = scv;
        }
        __syncthreads();
        const float* ep = enc + ((size_t)b * SEQ + st) * ENC + eg;
        int sr = 0;
        for (; sr + 4 <= tlen; sr += 4) {
            a0 += sc[sr + 0][h] * ep[(size_t)(sr + 0) * ENC];
            a1 += sc[sr + 1][h] * ep[(size_t)(sr + 1) * ENC];
            a2 += sc[sr + 2][h] * ep[(size_t)(sr + 2) * ENC];
            a3 += sc[sr + 3][h] * ep[(size_t)(sr + 3) * ENC];
        }
        for (; sr < tlen; sr++)
            a0 += sc[sr][h] * ep[(size_t)sr * ENC];
    }
    g_ctx[b][h * ENC + eg] = (a0 + a1) + (a2 + a3);
}

// ---------------- K4: context @ Wfc + bfc ----------------
__global__ void __launch_bounds__(256) k4_final(const float* __restrict__ Wfc,
                                                const float* __restrict__ bfc,
                                                float* __restrict__ out_ctx) {
    int et = blockIdx.x, bg = blockIdx.y;
    int tx = threadIdx.x & 31;
    int js = threadIdx.x >> 5;
    int e  = et * 32 + tx;
    int j0 = js * 512;
    float a0 = 0.f, a1 = 0.f, a2 = 0.f, a3 = 0.f;
    const float* c0 = g_ctx[bg * 4 + 0];
    const float* c1 = g_ctx[bg * 4 + 1];
    const float* c2 = g_ctx[bg * 4 + 2];
    const float* c3 = g_ctx[bg * 4 + 3];
    #pragma unroll 8
    for (int j = j0; j < j0 + 512; j++) {
        float w = Wfc[(size_t)j * ENC + e];
        a0 += c0[j] * w;
        a1 += c1[j] * w;
        a2 += c2[j] * w;
        a3 += c3[j] * w;
    }
    __shared__ float red[8][4][32];
    red[js][0][tx] = a0; red[js][1][tx] = a1;
    red[js][2][tx] = a2; red[js][3][tx] = a3;
    __syncthreads();
    if (js < 4) {
        int bb = js;
        float s = 0.f;
        #pragma unroll
        for (int jj = 0; jj < 8; jj++) s += red[jj][bb][tx];
        out_ctx[(bg * 4 + bb) * ENC + e] = s + bfc[e];
    }
}

// ---------------- launch ----------------
extern "C" void kernel_launch(void* const* d_in, const int* in_sizes, int n_in,
                              void* d_out, int out_size) {
    const float* enc   = (const float*)d_in[0];
    const float* dec   = (const float*)d_in[1];
    const float* kappa = (const float*)d_in[2];
    const float* mask  = (const float*)d_in[3];
    const float* Wv    = (const float*)d_in[4];
    const float* bv    = (const float*)d_in[5];
    const float* Wq    = (const float*)d_in[6];
    const float* bq    = (const float*)d_in[7];
    const float* Wf    = (const float*)d_in[8];
    const float* bf    = (const float*)d_in[9];
    const float* Wb    = (const float*)d_in[10];
    const float* bb    = (const float*)d_in[11];
    const float* Wk    = (const float*)d_in[12];
    const float* bk    = (const float*)d_in[13];
    const float* Wfc   = (const float*)d_in[14];
    const float* bfc   = (const float*)d_in[15];

    float* out_ctx   = (float*)d_out;
    float* out_kappa = out_ctx + BS * ENC;
    float* out_score = out_kappa + BS * HEADS;

    cudaFuncSetAttribute(k2a_mma, cudaFuncAttributeMaxDynamicSharedMemorySize, SMEM_DYN);

    cudaMemsetAsync(out_score, 0, (size_t)BS * SEQ * HEADS * sizeof(float), 0);
    k_prep<<<672, 256>>>(Wv, dec, Wq, bq, bv, kappa, Wb, bb, Wk, bk, out_kappa);
    k0b_compact<<<1, 256>>>();
    kE_split<<<MAXTILES, 256>>>(enc);
    k2a_mma<<<256, 128, SMEM_DYN>>>(Wf);
    k2bc_score_ctx<<<dim3(BS, 16), 256>>>(enc, bf, mask, out_score);
    k4_final<<<dim3(16, 8), 256>>>(Wfc, bfc, out_ctx);
}

// round 11
// speedup vs baseline: 4.0603x; 1.2094x over previous
#include <cuda_runtime.h>
#include <cuda_bf16.h>
#include <math.h>
#include <stdint.h>

#define BS    32
#define SEQ   2048
#define ENC   512
#define HEADS 8
#define IH    1024
#define DECIN 1024
#define SENT  0xFFFFFFFFu

#define MT 64            // rows per m-tile (k2a)
#define NT 64            // j per n-tile
#define NJT (IH / NT)    // 16
#define KC 64
#define MAXTILES 512     // kE 128-row tiles upper bound

// ---------------- scratch ----------------
__device__ float         g_qv[BS][IH];
__device__ float         g_beta[BS][HEADS];
__device__ float         g_kap[BS][HEADS];
__device__ int           g_lo[BS];
__device__ int           g_hi[BS];
__device__ unsigned      g_rows[BS * SEQ + 128];
__device__ float         g_pf[BS][SEQ][NJT * HEADS];
__device__ float         g_ctx[BS][HEADS * ENC];
__device__ __nv_bfloat16 g_WvThi[IH * ENC];
__device__ __nv_bfloat16 g_WvTlo[IH * ENC];
__device__ __nv_bfloat16 g_Ahi[(size_t)MAXTILES * 128 * ENC];
__device__ __nv_bfloat16 g_Alo[(size_t)MAXTILES * 128 * ENC];

__device__ __forceinline__ float softplusf(float x) {
    return fmaxf(x, 0.f) + log1pf(expf(-fabsf(x)));
}

#define SW128(x) ((x) ^ (((x) >> 3) & 0x70))

__device__ __forceinline__ uint32_t smem_u32(const void* p) {
    uint32_t a;
    asm("{ .reg .u64 t; cvta.to.shared.u64 t, %1; cvt.u32.u64 %0, t; }" : "=r"(a) : "l"(p));
    return a;
}
__device__ __forceinline__ void ldsm4(uint32_t* r, uint32_t addr) {
    asm volatile("ldmatrix.sync.aligned.m8n8.x4.shared.b16 {%0,%1,%2,%3}, [%4];"
                 : "=r"(r[0]), "=r"(r[1]), "=r"(r[2]), "=r"(r[3]) : "r"(addr));
}
__device__ __forceinline__ void mma16816(float* c, const uint32_t* a,
                                         uint32_t b0, uint32_t b1) {
    asm volatile("mma.sync.aligned.m16n8k16.row.col.f32.bf16.bf16.f32 "
                 "{%0,%1,%2,%3}, {%4,%5,%6,%7}, {%8,%9}, {%0,%1,%2,%3};"
                 : "+f"(c[0]), "+f"(c[1]), "+f"(c[2]), "+f"(c[3])
                 : "r"(a[0]), "r"(a[1]), "r"(a[2]), "r"(a[3]), "r"(b0), "r"(b1));
}
__device__ __forceinline__ void cp16(uint32_t dst, const void* src) {
    asm volatile("cp.async.cg.shared.global [%0], [%1], 16;" :: "r"(dst), "l"(src));
}
#define CP_COMMIT() asm volatile("cp.async.commit_group;" ::: "memory")
#define CP_WAIT(n)  asm volatile("cp.async.wait_group %0;" :: "n"(n) : "memory")

// ---------------- k_prep: merged kW_split (0..511) + k1_query (512..639) + k0_heads (640..671)
__global__ void __launch_bounds__(256) k_prep(const float* __restrict__ Wv,
                                              const float* __restrict__ dec,
                                              const float* __restrict__ Wq,
                                              const float* __restrict__ bq,
                                              const float* __restrict__ bv,
                                              const float* __restrict__ kappa_in,
                                              const float* __restrict__ Wb,
                                              const float* __restrict__ bb,
                                              const float* __restrict__ Wk,
                                              const float* __restrict__ bk,
                                              float* __restrict__ out_kappa) {
    __shared__ float smem[4 * DECIN + 4 * 4 * 64];
    int bid = blockIdx.x;

    if (bid < 512) {
        float (*s)[33] = (float (*)[33])smem;
        int k0 = (bid & 15) * 32, j0 = (bid >> 4) * 32;
        int jl = threadIdx.x & 31, kq = threadIdx.x >> 5;
        #pragma unroll
        for (int i = 0; i < 4; i++)
            s[kq * 4 + i][jl] = Wv[(size_t)(k0 + kq * 4 + i) * IH + j0 + jl];
        __syncthreads();
        int jr = threadIdx.x >> 3;
        int kg = (threadIdx.x & 7) * 4;
        __nv_bfloat16 hi[4], lo[4];
        #pragma unroll
        for (int i = 0; i < 4; i++) {
            float x = s[kg + i][jr];
            hi[i] = __float2bfloat16(x);
            lo[i] = __float2bfloat16(x - __bfloat162float(hi[i]));
        }
        size_t dst = (size_t)(j0 + jr) * ENC + k0 + kg;
        *(uint2*)(g_WvThi + dst) = *(const uint2*)hi;
        *(uint2*)(g_WvTlo + dst) = *(const uint2*)lo;
    } else if (bid < 640) {
        int id = bid - 512;
        int jt = id & 15, bg = id >> 4;
        int c  = threadIdx.x & 63;
        int ks = threadIdx.x >> 6;
        int j  = jt * 64 + c;
        float (*sdec)[DECIN] = (float (*)[DECIN])smem;
        float (*pacc)[4][64] = (float (*)[4][64])(smem + 4 * DECIN);
        for (int i = threadIdx.x; i < 4 * DECIN; i += 256) {
            int bb2 = i >> 10, k = i & (DECIN - 1);
            sdec[bb2][k] = dec[(bg * 4 + bb2) * DECIN + k];
        }
        __syncthreads();
        float a0 = 0.f, a1 = 0.f, a2 = 0.f, a3 = 0.f;
        int k0 = ks * 256;
        #pragma unroll 4
        for (int k = k0; k < k0 + 256; k++) {
            float w = Wq[k * IH + j];
            a0 += sdec[0][k] * w; a1 += sdec[1][k] * w;
            a2 += sdec[2][k] * w; a3 += sdec[3][k] * w;
        }
        pacc[ks][0][c] = a0; pacc[ks][1][c] = a1;
        pacc[ks][2][c] = a2; pacc[ks][3][c] = a3;
        __syncthreads();
        if (ks == 0) {
            float add = bq[j] + bv[j];
            #pragma unroll
            for (int bb2 = 0; bb2 < 4; bb2++) {
                float s2 = pacc[0][bb2][c] + pacc[1][bb2][c] + pacc[2][bb2][c] + pacc[3][bb2][c];
                g_qv[bg * 4 + bb2][j] = s2 + add;
            }
        }
    } else {
        int b = bid - 640;
        float* sdec = smem;
        float* sbeta = smem + DECIN;
        float* skap  = smem + DECIN + HEADS;
        for (int i = threadIdx.x; i < DECIN; i += 256)
            sdec[i] = dec[b * DECIN + i];
        __syncthreads();
        int w = threadIdx.x >> 5, lane = threadIdx.x & 31;
        #pragma unroll
        for (int rep = 0; rep < 2; rep++) {
            int p = w + rep * 8;
            int h = p & 7;
            const float* W = (p < 8) ? Wb : Wk;
            float acc = 0.f;
            for (int k = lane; k < DECIN; k += 32) acc += sdec[k] * W[k * HEADS + h];
            #pragma unroll
            for (int off = 16; off >= 1; off >>= 1)
                acc += __shfl_xor_sync(0xffffffffu, acc, off);
            if (lane == 0) {
                if (p < 8) {
                    float bv2 = softplusf(acc + bb[h]);
                    sbeta[h] = bv2;
                    g_beta[b][h] = bv2;
                } else {
                    float kv = kappa_in[b * HEADS + h] + softplusf(acc + bk[h]);
                    skap[h] = kv;
                    g_kap[b][h] = kv;
                    out_kappa[b * HEADS + h] = kv;
                }
            }
        }
        __syncthreads();
        if (threadIdx.x == 0) {
            float lof = 1e30f, hif = -1e30f;
            for (int h = 0; h < HEADS; h++) {
                float R = sqrtf(110.f / sbeta[h]);
                lof = fminf(lof, skap[h] - R);
                hif = fmaxf(hif, skap[h] + R);
            }
            int lo, hi;
            if (hif < 0.f || lof > (float)(SEQ - 1)) { lo = 0; hi = -1; }
            else {
                lo = (int)floorf(lof); if (lo < 0) lo = 0;
                hi = (int)ceilf(hif);  if (hi > SEQ - 1) hi = SEQ - 1;
            }
            g_lo[b] = lo; g_hi[b] = hi;
        }
    }
}

// ---------------- kE: inline compaction + split enc rows into bf16 hi/lo ----------------
// grid (MAXTILES, 8): tile = bx (128 rows), by = 64-col slice. block 256.
// by==0 blocks also write g_rows. Compaction offsets recomputed per block (cheap).
__global__ void __launch_bounds__(256) kE_split(const float* __restrict__ enc) {
    __shared__ int soff[BS + 1];
    __shared__ int snt;
    int tid = threadIdx.x;
    if (tid == 0) {
        int off = 0;
        for (int b = 0; b < BS; b++) {
            soff[b] = off;
            int w = g_hi[b] - g_lo[b] + 1;
            if (w < 0) w = 0;
            off += w;
        }
        soff[BS] = off;
        int nt = (off + 127) / 128;
        if (nt < 1) nt = 1;
        snt = nt;
    }
    __syncthreads();
    int tile = blockIdx.x;
    if (tile >= snt) return;

    int row  = tid >> 1;
    int half = tid & 1;
    int grow = tile * 128 + row;
    int total = soff[BS];

    unsigned m = SENT;
    if (grow < total) {
        int b = 0;
        #pragma unroll 8
        while (b < BS - 1 && grow >= soff[b + 1]) b++;
        m = ((unsigned)b << 16) | (unsigned)(g_lo[b] + (grow - soff[b]));
    }
    if (blockIdx.y == 0 && half == 0)
        g_rows[grow] = m;

    int colb = blockIdx.y * 64 + half * 32;
    size_t dbase = (size_t)grow * ENC + colb;
    if (m == SENT) {
        uint4 z = make_uint4(0, 0, 0, 0);
        #pragma unroll
        for (int q = 0; q < 4; q++) {
            ((uint4*)(g_Ahi + dbase))[q] = z;
            ((uint4*)(g_Alo + dbase))[q] = z;
        }
        return;
    }
    const float4* src = (const float4*)(enc + ((size_t)(m >> 16) * SEQ + (m & 0xFFFF)) * ENC + colb);
    #pragma unroll
    for (int q = 0; q < 4; q++) {
        float4 v0 = src[q * 2], v1 = src[q * 2 + 1];
        float x[8] = {v0.x, v0.y, v0.z, v0.w, v1.x, v1.y, v1.z, v1.w};
        __nv_bfloat16 hi[8], lo[8];
        #pragma unroll
        for (int i = 0; i < 8; i++) {
            hi[i] = __float2bfloat16(x[i]);
            lo[i] = __float2bfloat16(x[i] - __bfloat162float(hi[i]));
        }
        ((uint4*)(g_Ahi + dbase))[q] = *(const uint4*)hi;
        ((uint4*)(g_Alo + dbase))[q] = *(const uint4*)lo;
    }
}

// ---------------- K2a: pipelined warp-MMA bf16-split GEMM + tanh + partial @Wf ----------------
#define ST_STRIDE 32768
#define OFF_AH 0
#define OFF_AL 8192
#define OFF_BH 16384
#define OFF_BL 24576
#define OFF_WF   (2 * ST_STRIDE)
#define OFF_META (OFF_WF + 2048)
#define SMEM_DYN (OFF_META + 256 + 1024)

__global__ void __launch_bounds__(128) k2a_mma(const float* __restrict__ Wf) {
    extern __shared__ char dsm[];
    uint32_t b0 = smem_u32(dsm);
    uint32_t ab = (b0 + 1023u) & ~1023u;
    char* dyn = dsm + (ab - b0);
    float*    sWf   = (float*)(dyn + OFF_WF);
    unsigned* smeta = (unsigned*)(dyn + OFF_META);
    __shared__ int s_tt;

    int tid  = threadIdx.x;
    int wid  = tid >> 5, lane = tid & 31;

    if (tid == 0) {
        int off = 0;
        for (int b = 0; b < BS; b++) {
            int w = g_hi[b] - g_lo[b] + 1;
            if (w > 0) off += w;
        }
        int n64 = (off + MT - 1) / MT;
        if (n64 < 1) n64 = 1;
        s_tt = n64 * NJT;
    }
    __syncthreads();
    int total_tiles = s_tt;

    int wm = wid * 16;
    uint32_t a_rb  = (uint32_t)((wm + (lane & 15)) * 128 + ((lane & 16) ? 16 : 0));
    uint32_t a_msk = (a_rb >> 3) & 0x70;
    uint32_t b_rb[4], b_msk[4];
    #pragma unroll
    for (int p = 0; p < 4; p++) {
        int n = p * 16 + (lane & 7) + ((lane & 16) ? 8 : 0);
        b_rb[p]  = (uint32_t)(n * 128 + ((lane & 8) ? 16 : 0));
        b_msk[p] = (b_rb[p] >> 3) & 0x70;
    }

    int srow = tid >> 1, shalf = tid & 1;

    for (int t = blockIdx.x; t < total_tiles; t += gridDim.x) {
        int mtile = t >> 4;
        int jt    = t & 15;
        int jbase = jt * NT;

        __syncthreads();
        if (tid < MT) smeta[tid] = g_rows[mtile * MT + tid];
        #pragma unroll
        for (int i = 0; i < 4; i++) sWf[tid + i * 128] = Wf[jbase * 8 + tid + i * 128];

        const char* Ah_base = (const char*)(g_Ahi + (size_t)(mtile * MT + srow) * ENC) + shalf * 64;
        const char* Al_base = (const char*)(g_Alo + (size_t)(mtile * MT + srow) * ENC) + shalf * 64;
        const char* Bh_base = (const char*)(g_WvThi + (size_t)(jbase + srow) * ENC) + shalf * 64;
        const char* Bl_base = (const char*)(g_WvTlo + (size_t)(jbase + srow) * ENC) + shalf * 64;

        #define STAGE(kc_, buf_) do { \
            uint32_t sb_ = ab + (buf_) * ST_STRIDE; \
            _Pragma("unroll") \
            for (int q = 0; q < 4; q++) { \
                uint32_t o_ = SW128((uint32_t)(srow * 128 + shalf * 64 + q * 16)); \
                cp16(sb_ + OFF_AH + o_, Ah_base + (kc_) * 128 + q * 16); \
                cp16(sb_ + OFF_AL + o_, Al_base + (kc_) * 128 + q * 16); \
                cp16(sb_ + OFF_BH + o_, Bh_base + (kc_) * 128 + q * 16); \
                cp16(sb_ + OFF_BL + o_, Bl_base + (kc_) * 128 + q * 16); \
            } \
        } while (0)

        STAGE(0, 0);
        CP_COMMIT();

        float acc[8][4];
        #pragma unroll
        for (int nf = 0; nf < 8; nf++)
            #pragma unroll
            for (int q = 0; q < 4; q++) acc[nf][q] = 0.f;

        #pragma unroll
        for (int kc = 0; kc < ENC / KC; kc++) {
            __syncthreads();
            if (kc < ENC / KC - 1) {
                STAGE(kc + 1, (kc + 1) & 1);
                CP_COMMIT();
                CP_WAIT(1);
            } else {
                CP_WAIT(0);
            }
            __syncthreads();

            uint32_t mb = ab + (kc & 1) * ST_STRIDE;
            #pragma unroll
            for (int ks = 0; ks < 4; ks++) {
                uint32_t ah[4], al[4];
                ldsm4(ah, mb + OFF_AH + ((a_rb + ks * 32) ^ a_msk));
                ldsm4(al, mb + OFF_AL + ((a_rb + ks * 32) ^ a_msk));
                uint32_t bh[4][4], bl[4][4];
                #pragma unroll
                for (int p = 0; p < 4; p++) {
                    ldsm4(bh[p], mb + OFF_BH + ((b_rb[p] + ks * 32) ^ b_msk[p]));
                    ldsm4(bl[p], mb + OFF_BL + ((b_rb[p] + ks * 32) ^ b_msk[p]));
                }
                #pragma unroll
                for (int p = 0; p < 4; p++) {
                    mma16816(acc[p * 2],     ah, bh[p][0], bh[p][1]);
                    mma16816(acc[p * 2 + 1], ah, bh[p][2], bh[p][3]);
                }
                #pragma unroll
                for (int p = 0; p < 4; p++) {
                    mma16816(acc[p * 2],     ah, bl[p][0], bl[p][1]);
                    mma16816(acc[p * 2 + 1], ah, bl[p][2], bl[p][3]);
                }
                #pragma unroll
                for (int p = 0; p < 4; p++) {
                    mma16816(acc[p * 2],     al, bh[p][0], bh[p][1]);
                    mma16816(acc[p * 2 + 1], al, bh[p][2], bh[p][3]);
                }
            }
        }
        #undef STAGE

        // ---- epilogue ----
        int r0 = wm + (lane >> 2);
        int r1 = r0 + 8;
        unsigned m0 = smeta[r0], m1 = smeta[r1];
        const float* qv0 = &g_qv[(m0 != SENT) ? (m0 >> 16) : 0][jbase];
        const float* qv1 = &g_qv[(m1 != SENT) ? (m1 >> 16) : 0][jbase];
        float pf0[8], pf1[8];
        #pragma unroll
        for (int h = 0; h < 8; h++) { pf0[h] = 0.f; pf1[h] = 0.f; }
        #pragma unroll
        for (int nf = 0; nf < 8; nf++) {
            int jl = nf * 8 + 2 * (lane & 3);
            float hv00 = (m0 != SENT) ? tanhf(qv0[jl]     + acc[nf][0]) : 0.f;
            float hv01 = (m0 != SENT) ? tanhf(qv0[jl + 1] + acc[nf][1]) : 0.f;
            float hv10 = (m1 != SENT) ? tanhf(qv1[jl]     + acc[nf][2]) : 0.f;
            float hv11 = (m1 != SENT) ? tanhf(qv1[jl + 1] + acc[nf][3]) : 0.f;
            const float* w0 = &sWf[jl * 8];
            const float* w1 = &sWf[(jl + 1) * 8];
            #pragma unroll
            for (int h = 0; h < 8; h++) {
                pf0[h] += hv00 * w0[h] + hv01 * w1[h];
                pf1[h] += hv10 * w0[h] + hv11 * w1[h];
            }
        }
        #pragma unroll
        for (int h = 0; h < 8; h++) {
            pf0[h] += __shfl_xor_sync(0xffffffffu, pf0[h], 1);
            pf0[h] += __shfl_xor_sync(0xffffffffu, pf0[h], 2);
            pf1[h] += __shfl_xor_sync(0xffffffffu, pf1[h], 1);
            pf1[h] += __shfl_xor_sync(0xffffffffu, pf1[h], 2);
        }
        if ((lane & 3) == 0) {
            if (m0 != SENT) {
                float* dst = &g_pf[m0 >> 16][m0 & 0xFFFF][jt * 8];
                *(float4*)dst       = make_float4(pf0[0], pf0[1], pf0[2], pf0[3]);
                *(float4*)(dst + 4) = make_float4(pf0[4], pf0[5], pf0[6], pf0[7]);
            }
            if (m1 != SENT) {
                float* dst = &g_pf[m1 >> 16][m1 & 0xFFFF][jt * 8];
                *(float4*)dst       = make_float4(pf1[0], pf1[1], pf1[2], pf1[3]);
                *(float4*)(dst + 4) = make_float4(pf1[4], pf1[5], pf1[6], pf1[7]);
            }
        }
    }
}

// ---------------- K2bc: partials -> score -> context ----------------
__global__ void __launch_bounds__(256) k2bc_score_ctx(const float* __restrict__ enc,
                                                      const float* __restrict__ bf,
                                                      const float* __restrict__ mask,
                                                      float* __restrict__ out_score) {
    int b  = blockIdx.x;
    int et = blockIdx.y;
    int lo = g_lo[b], hi = g_hi[b];
    int tx = threadIdx.x & 31;
    int h  = threadIdx.x >> 5;
    int eg = et * 32 + tx;

    __shared__ float sc[256][8];
    float a0 = 0.f, a1 = 0.f, a2 = 0.f, a3 = 0.f;

    for (int st = lo; st <= hi; st += 256) {
        int tlen = hi - st + 1; if (tlen > 256) tlen = 256;
        __syncthreads();
        for (int idx = threadIdx.x; idx < tlen * 8; idx += 256) {
            int sr = idx >> 3, hh = idx & 7;
            int s = st + sr;
            const float* p = g_pf[b][s];
            float f = bf[hh];
            #pragma unroll
            for (int pp = 0; pp < 16; pp++) f += p[pp * 8 + hh];
            float alpha = softplusf(f) * mask[b * SEQ + s];
            float d = g_kap[b][hh] - (float)s;
            float scv = alpha * expf(-g_beta[b][hh] * d * d);
            sc[sr][hh] = scv;
            if (et == 0)
                out_score[((size_t)b * SEQ + s) * HEADS + hh] = scv;
        }
        __syncthreads();
        const float* ep = enc + ((size_t)b * SEQ + st) * ENC + eg;
        int sr = 0;
        for (; sr + 4 <= tlen; sr += 4) {
            a0 += sc[sr + 0][h] * ep[(size_t)(sr + 0) * ENC];
            a1 += sc[sr + 1][h] * ep[(size_t)(sr + 1) * ENC];
            a2 += sc[sr + 2][h] * ep[(size_t)(sr + 2) * ENC];
            a3 += sc[sr + 3][h] * ep[(size_t)(sr + 3) * ENC];
        }
        for (; sr < tlen; sr++)
            a0 += sc[sr][h] * ep[(size_t)sr * ENC];
    }
    g_ctx[b][h * ENC + eg] = (a0 + a1) + (a2 + a3);
}

// ---------------- K4: context @ Wfc + bfc ----------------
__global__ void __launch_bounds__(256) k4_final(const float* __restrict__ Wfc,
                                                const float* __restrict__ bfc,
                                                float* __restrict__ out_ctx) {
    int et = blockIdx.x, bg = blockIdx.y;
    int tx = threadIdx.x & 31;
    int js = threadIdx.x >> 5;
    int e  = et * 32 + tx;
    int j0 = js * 512;
    float a0 = 0.f, a1 = 0.f, a2 = 0.f, a3 = 0.f;
    const float* c0 = g_ctx[bg * 4 + 0];
    const float* c1 = g_ctx[bg * 4 + 1];
    const float* c2 = g_ctx[bg * 4 + 2];
    const float* c3 = g_ctx[bg * 4 + 3];
    #pragma unroll 8
    for (int j = j0; j < j0 + 512; j++) {
        float w = Wfc[(size_t)j * ENC + e];
        a0 += c0[j] * w;
        a1 += c1[j] * w;
        a2 += c2[j] * w;
        a3 += c3[j] * w;
    }
    __shared__ float red[8][4][32];
    red[js][0][tx] = a0; red[js][1][tx] = a1;
    red[js][2][tx] = a2; red[js][3][tx] = a3;
    __syncthreads();
    if (js < 4) {
        int bb = js;
        float s = 0.f;
        #pragma unroll
        for (int jj = 0; jj < 8; jj++) s += red[jj][bb][tx];
        out_ctx[(bg * 4 + bb) * ENC + e] = s + bfc[e];
    }
}

// ---------------- launch ----------------
extern "C" void kernel_launch(void* const* d_in, const int* in_sizes, int n_in,
                              void* d_out, int out_size) {
    const float* enc   = (const float*)d_in[0];
    const float* dec   = (const float*)d_in[1];
    const float* kappa = (const float*)d_in[2];
    const float* mask  = (const float*)d_in[3];
    const float* Wv    = (const float*)d_in[4];
    const float* bv    = (const float*)d_in[5];
    const float* Wq    = (const float*)d_in[6];
    const float* bq    = (const float*)d_in[7];
    const float* Wf    = (const float*)d_in[8];
    const float* bf    = (const float*)d_in[9];
    const float* Wb    = (const float*)d_in[10];
    const float* bb    = (const float*)d_in[11];
    const float* Wk    = (const float*)d_in[12];
    const float* bk    = (const float*)d_in[13];
    const float* Wfc   = (const float*)d_in[14];
    const float* bfc   = (const float*)d_in[15];

    float* out_ctx   = (float*)d_out;
    float* out_kappa = out_ctx + BS * ENC;
    float* out_score = out_kappa + BS * HEADS;

    cudaFuncSetAttribute(k2a_mma, cudaFuncAttributeMaxDynamicSharedMemorySize, SMEM_DYN);

    cudaMemsetAsync(out_score, 0, (size_t)BS * SEQ * HEADS * sizeof(float), 0);
    k_prep<<<672, 256>>>(Wv, dec, Wq, bq, bv, kappa, Wb, bb, Wk, bk, out_kappa);
    kE_split<<<dim3(MAXTILES, 8), 256>>>(enc);
    k2a_mma<<<256, 128, SMEM_DYN>>>(Wf);
    k2bc_score_ctx<<<dim3(BS, 16), 256>>>(enc, bf, mask, out_score);
    k4_final<<<dim3(16, 8), 256>>>(Wfc, bfc, out_ctx);
}